// round 12
// baseline (speedup 1.0000x reference)
#include <cuda_runtime.h>
#include <cuda_fp16.h>
#include <math.h>
#include <stdint.h>

// Problem constants
#define B2   2
#define L2   1024
#define D2   768
#define H2   12
#define DH   64
#define BH   (B2*H2)        // 24
#define BL   (B2*L2)        // 2048
#define N3D  (3*D2)         // 2304
#define CHK  128            // chunk length
#define NC   (L2/CHK)       // 8
#define GK   768            // shared K dim of all GEMMs
#define OUT_ELEMS (BL*D2)   // 1572864

// ---------------- scratch (device globals; no allocation allowed) ----------
__device__ float g_kraw[BL*D2];      // k section fp32 (pre-gate)
__device__ float g_kv[BH*NC*DH*DH];
__device__ float g_ksum[BH*NC*DH];
__device__ float g_sprev[BH*NC*DH*DH];
__device__ float g_ksp[BH*NC*DH];
// fp16 operands (16B-aligned for cp.async / vector loads)
__device__ __align__(256) __half g_an[BL*GK];       // LN(x) fp16
__device__ __align__(256) __half g_x16[BL*GK];      // raw x fp16
__device__ __align__(256) __half g_at16[BL*D2];     // attn out fp16
__device__ __align__(256) __half g_qf16[BH*L2*DH];
__device__ __align__(256) __half g_kf16[BH*L2*DH];
__device__ __align__(256) __half g_vf16[BH*L2*DH];
__device__ __align__(256) __half g_wtq[N3D*GK];     // W_qkv^T fp16
__device__ __align__(256) __half g_wtg[D2*GK];      // W_gate^T fp16
__device__ __align__(256) __half g_wtp[D2*GK];      // W_proj^T fp16

// =================== helpers ===============================================
__device__ __forceinline__ uint32_t smem_u32(const void* p) {
    uint32_t a;
    asm("{ .reg .u64 t; cvta.to.shared.u64 t, %1; cvt.u32.u64 %0, t; }"
        : "=r"(a) : "l"(p));
    return a;
}
__device__ __forceinline__ uint32_t sw128(uint32_t off) {
    return off ^ ((off >> 3) & 0x70);
}

#define LDSM4(r0, r1, r2, r3, addr) \
    asm volatile("ldmatrix.sync.aligned.m8n8.x4.shared.b16 {%0,%1,%2,%3}, [%4];" \
        : "=r"(r0), "=r"(r1), "=r"(r2), "=r"(r3) : "r"(addr))

#define MMA_F16(d, a, b) \
    asm volatile("mma.sync.aligned.m16n8k16.row.col.f32.f16.f16.f32 " \
        "{%0,%1,%2,%3},{%4,%5,%6,%7},{%8,%9},{%0,%1,%2,%3};" \
        : "+f"((d)[0]), "+f"((d)[1]), "+f"((d)[2]), "+f"((d)[3]) \
        : "r"((a)[0]), "r"((a)[1]), "r"((a)[2]), "r"((a)[3]), \
          "r"((b)[0]), "r"((b)[1]))

#define CP_ASYNC16(dst, src) \
    asm volatile("cp.async.cg.shared.global [%0], [%1], 16;" \
        :: "r"((uint32_t)(dst)), "l"(src))
#define CP_COMMIT() asm volatile("cp.async.commit_group;" ::: "memory")
#define CP_WAIT(n)  asm volatile("cp.async.wait_group %0;" :: "n"(n) : "memory")

// ------- fused: weight transposes + LayerNorm ------------------------------
// grid.x: [0, 2880) transpose tiles; [2880, 4928) ln rows. 256 threads.
#define NTRB ((N3D + D2 + D2) / 32 * (GK / 32))   // 120*24 = 2880

__global__ void lt_kernel(const float* __restrict__ Wq,
                          const float* __restrict__ Wg,
                          const float* __restrict__ Wp,
                          __half* __restrict__ wtq,
                          __half* __restrict__ wtg,
                          __half* __restrict__ wtp,
                          const float* __restrict__ x,
                          const float* __restrict__ lg,
                          const float* __restrict__ lb,
                          __half* __restrict__ an, __half* __restrict__ x16) {
    __shared__ float t[32][33];
    __shared__ float ss[6], sqs[6];
    int bid = blockIdx.x;
    int tid = threadIdx.x;
    if (bid < NTRB) {
        // ---- transpose tile ----
        int bx = bid % 120;
        int k0 = (bid / 120) * 32;
        const float* W; __half* Wt; int N;
        if (bx < N3D / 32)                { W = Wq; Wt = wtq; N = N3D; }
        else if (bx < N3D / 32 + D2 / 32) { W = Wg; Wt = wtg; N = D2; bx -= N3D / 32; }
        else                              { W = Wp; Wt = wtp; N = D2; bx -= N3D / 32 + D2 / 32; }
        int n0 = bx * 32;
        int tx = tid & 31, ty = tid >> 5;   // 32 x 8
        #pragma unroll
        for (int r = ty; r < 32; r += 8)
            t[r][tx] = W[(size_t)(k0 + r) * N + n0 + tx];
        __syncthreads();
        #pragma unroll
        for (int r = ty; r < 32; r += 8)
            Wt[(size_t)(n0 + r) * GK + k0 + tx] = __float2half_rn(t[tx][r]);
    } else {
        // ---- layernorm row ----
        int row = bid - NTRB;
        float4 v = make_float4(0.f, 0.f, 0.f, 0.f);
        if (tid < 192) v = ((const float4*)(x + (size_t)row * D2))[tid];
        float s  = v.x + v.y + v.z + v.w;
        float sq = v.x*v.x + v.y*v.y + v.z*v.z + v.w*v.w;
        #pragma unroll
        for (int o = 16; o; o >>= 1) {
            s  += __shfl_xor_sync(0xffffffffu, s,  o);
            sq += __shfl_xor_sync(0xffffffffu, sq, o);
        }
        if (tid < 192 && (tid & 31) == 0) { ss[tid >> 5] = s; sqs[tid >> 5] = sq; }
        __syncthreads();
        float ts = 0.f, tq = 0.f;
        #pragma unroll
        for (int w = 0; w < 6; w++) { ts += ss[w]; tq += sqs[w]; }
        float mean = ts * (1.f / D2);
        float var  = tq * (1.f / D2) - mean * mean;
        float inv  = rsqrtf(var + 1e-5f);
        if (tid < 192) {
            int cc = tid * 4;
            float4 gg = ((const float4*)lg)[tid];
            float4 bb = ((const float4*)lb)[tid];
            float n0 = (v.x - mean) * inv * gg.x + bb.x;
            float n1 = (v.y - mean) * inv * gg.y + bb.y;
            float n2 = (v.z - mean) * inv * gg.z + bb.z;
            float n3 = (v.w - mean) * inv * gg.w + bb.w;
            __half2 a01 = __floats2half2_rn(n0, n1);
            __half2 a23 = __floats2half2_rn(n2, n3);
            *(uint2*)(an + (size_t)row * D2 + cc) =
                make_uint2(*(uint32_t*)&a01, *(uint32_t*)&a23);
            __half2 x01 = __floats2half2_rn(v.x, v.y);
            __half2 x23 = __floats2half2_rn(v.z, v.w);
            *(uint2*)(x16 + (size_t)row * D2 + cc) =
                make_uint2(*(uint32_t*)&x01, *(uint32_t*)&x23);
        }
    }
}

// ---------------- fp16 mma.sync GEMM, 2-stage cp.async ---------------------
// EPI: 0 = plain fp32 C, 1 = sigmoid fp32 C, 2 = fused qkv epilogue
#define BKC 64
#define STG_A 0
#define STG_B 16384
#define STAGE_B 32768
#define NSTG 2
#define GEMM_SMEM_BYTES (NSTG * STAGE_B)   // 65536
#define NCHUNK (GK / BKC)   // 12

template <int EPI>
__device__ __forceinline__ void gemm_core(char* smem,
    const __half* __restrict__ Ap, const __half* __restrict__ Bp,
    const float* __restrict__ bias, float* __restrict__ C,
    int Nld, int cb0, int rb0,
    __half* __restrict__ qf, __half* __restrict__ vf,
    float* __restrict__ kraw)
{
    uint32_t sb = smem_u32(smem);
    int tid  = threadIdx.x;
    int wid  = tid >> 5, lane = tid & 31;
    int wm   = wid >> 2, wn = wid & 3;        // warp grid 2x4
    int m0   = wm * 64;
    int n0   = wn * 32;
    int lr   = lane & 7, g = lane >> 3;
    int arow = ((g & 1) << 3) + lr;
    int acolb = (g >> 1) << 4;
    int brow = ((g >> 1) << 3) + lr;
    int bcolb = (g & 1) << 4;

    int srow[4], sseg[4]; uint32_t soff[4];
    #pragma unroll
    for (int i = 0; i < 4; i++) {
        int idx = tid + 256 * i;
        srow[i] = idx >> 3;
        sseg[i] = idx & 7;
        soff[i] = sw128((uint32_t)(srow[i] * 128 + sseg[i] * 16));
    }

    float acc[4][4][4];
    #pragma unroll
    for (int mt = 0; mt < 4; mt++)
        #pragma unroll
        for (int nt = 0; nt < 4; nt++)
            #pragma unroll
            for (int q = 0; q < 4; q++) acc[mt][nt][q] = 0.f;

    {
        uint32_t db = sb;
        #pragma unroll
        for (int i = 0; i < 4; i++) {
            size_t off = (size_t)srow[i] * GK + sseg[i] * 8;
            CP_ASYNC16(db + STG_A + soff[i], Ap + off);
            CP_ASYNC16(db + STG_B + soff[i], Bp + off);
        }
        CP_COMMIT();
    }

    for (int c = 0; c < NCHUNK; c++) {
        int st = c & 1;
        CP_WAIT(0);
        __syncthreads();
        if (c + 1 < NCHUNK) {
            uint32_t db = sb + (st ^ 1) * STAGE_B;
            int k0 = (c + 1) * BKC;
            #pragma unroll
            for (int i = 0; i < 4; i++) {
                size_t off = (size_t)srow[i] * GK + k0 + sseg[i] * 8;
                CP_ASYNC16(db + STG_A + soff[i], Ap + off);
                CP_ASYNC16(db + STG_B + soff[i], Bp + off);
            }
            CP_COMMIT();
        }

        uint32_t sA = sb + st * STAGE_B;
        uint32_t sB = sA + STG_B;
        #pragma unroll
        for (int kt = 0; kt < 4; kt++) {
            uint32_t bf[4][2];
            #pragma unroll
            for (int t = 0; t < 2; t++) {
                uint32_t boff = sw128((uint32_t)((n0 + t * 16 + brow) * 128 + kt * 32 + bcolb));
                LDSM4(bf[2*t][0], bf[2*t][1], bf[2*t+1][0], bf[2*t+1][1], sB + boff);
            }
            #pragma unroll
            for (int mt = 0; mt < 4; mt++) {
                uint32_t aoff = sw128((uint32_t)((m0 + mt * 16 + arow) * 128 + kt * 32 + acolb));
                uint32_t af[4];
                LDSM4(af[0], af[1], af[2], af[3], sA + aoff);
                #pragma unroll
                for (int nt = 0; nt < 4; nt++)
                    MMA_F16(acc[mt][nt], af, bf[nt]);
            }
        }
        __syncthreads();
    }

    int rbase = rb0 + m0 + (lane >> 2);
    int cbase = cb0 + n0 + ((lane & 3) << 1);
    if (EPI < 2) {
        #pragma unroll
        for (int mt = 0; mt < 4; mt++) {
            #pragma unroll
            for (int nt = 0; nt < 4; nt++) {
                int col = cbase + nt * 8;
                float b0 = bias[col], b1 = bias[col + 1];
                #pragma unroll
                for (int h = 0; h < 2; h++) {
                    int row = rbase + mt * 16 + h * 8;
                    float o0 = acc[mt][nt][2*h + 0] + b0;
                    float o1 = acc[mt][nt][2*h + 1] + b1;
                    if (EPI == 1) {
                        o0 = 1.f / (1.f + expf(-o0));
                        o1 = 1.f / (1.f + expf(-o1));
                    }
                    *(float2*)(C + (size_t)row * Nld + col) = make_float2(o0, o1);
                }
            }
        }
    } else {
        // qkv epilogue: q -> elu+1 fp16 head layout; v -> fp16 head layout;
        //               k -> fp32 kraw (gate applied later inside chunk_kv)
        int sec = cb0 / D2;      // 0=q, 1=k, 2=v (tile never straddles sections)
        if (sec == 1) {
            #pragma unroll
            for (int mt = 0; mt < 4; mt++) {
                #pragma unroll
                for (int nt = 0; nt < 4; nt++) {
                    int col = cbase + nt * 8;
                    int cc  = col - D2;
                    float b0 = bias[col], b1 = bias[col + 1];
                    #pragma unroll
                    for (int h = 0; h < 2; h++) {
                        int row = rbase + mt * 16 + h * 8;
                        float o0 = acc[mt][nt][2*h + 0] + b0;
                        float o1 = acc[mt][nt][2*h + 1] + b1;
                        *(float2*)(kraw + (size_t)row * D2 + cc) = make_float2(o0, o1);
                    }
                }
            }
        } else {
            __half* dst = (sec == 0) ? qf : vf;
            #pragma unroll
            for (int mt = 0; mt < 4; mt++) {
                #pragma unroll
                for (int nt = 0; nt < 4; nt++) {
                    int col = cbase + nt * 8;
                    int cc  = col - sec * D2;
                    int hh = cc >> 6, d = cc & 63;
                    float b0 = bias[col], b1 = bias[col + 1];
                    #pragma unroll
                    for (int h = 0; h < 2; h++) {
                        int row = rbase + mt * 16 + h * 8;
                        float o0 = acc[mt][nt][2*h + 0] + b0;
                        float o1 = acc[mt][nt][2*h + 1] + b1;
                        if (sec == 0) {
                            o0 = (o0 > 0.f) ? (o0 + 1.f) : expf(o0);
                            o1 = (o1 > 0.f) ? (o1 + 1.f) : expf(o1);
                        }
                        int b = row >> 10, l = row & 1023;
                        size_t o = ((size_t)(b * H2 + hh) * L2 + l) * DH + d;
                        *(__half2*)(dst + o) = __floats2half2_rn(o0, o1);
                    }
                }
            }
        }
    }
}

// fused QKV + gate GEMM: bx<18 -> QKV tile (fused epilogue), bx>=18 -> gate
__global__ void __launch_bounds__(256, 2) gemm_qkv_gate(
    const __half* __restrict__ xn,  const __half* __restrict__ wq,
    const float* __restrict__ bq,
    __half* __restrict__ qf, __half* __restrict__ vf, float* __restrict__ kraw,
    const __half* __restrict__ x16, const __half* __restrict__ wg,
    const float* __restrict__ bg,   float* __restrict__ gateC)
{
    extern __shared__ char smem[];
    int bx = blockIdx.x, by = blockIdx.y;
    if (bx < N3D / 128) {
        gemm_core<2>(smem, xn + (size_t)by * 128 * GK,
                     wq + (size_t)bx * 128 * GK, bq, nullptr, 0,
                     bx * 128, by * 128, qf, vf, kraw);
    } else {
        int b2 = bx - N3D / 128;
        gemm_core<1>(smem, x16 + (size_t)by * 128 * GK,
                     wg + (size_t)b2 * 128 * GK, bg, gateC, D2,
                     b2 * 128, by * 128, nullptr, nullptr, nullptr);
    }
}

__global__ void __launch_bounds__(256, 2) gemm_proj(
    const __half* __restrict__ at16, const __half* __restrict__ wp,
    const float* __restrict__ bp,    float* __restrict__ outC)
{
    extern __shared__ char smem[];
    gemm_core<0>(smem, at16 + (size_t)blockIdx.y * 128 * GK,
                 wp + (size_t)blockIdx.x * 128 * GK, bp, outC, D2,
                 blockIdx.x * 128, blockIdx.y * 128, nullptr, nullptr, nullptr);
}

// --------- per-chunk: fused kprep + K^T V via MMA + ksum + kf16 ------------
__global__ void chunk_kv_kernel(const float* __restrict__ kraw,
                                const float* __restrict__ gate,
                                const __half* __restrict__ vf,
                                __half* __restrict__ kf,
                                float* __restrict__ kv,
                                float* __restrict__ ksum) {
    __shared__ __half sm2[2 * 64 * 136];
    __half* Kt = sm2;
    __half* Vt = sm2 + 64 * 136;
    int c = blockIdx.x, bh = blockIdx.y;
    int bb = bh / H2, hh = bh - bb * H2;
    int tid = threadIdx.x;   // 256
    int wid = tid >> 5, lane = tid & 31;
    const __half* vp = vf + (size_t)(bh * L2 + c * CHK) * DH;
    size_t blbase = (size_t)(bb * L2 + c * CHK);
    __half* kfp = kf + (size_t)(bh * L2 + c * CHK) * DH;
    for (int i = tid; i < CHK * DH; i += 256) {
        int t = i >> 6, d = i & 63;
        size_t gi = (blbase + t) * D2 + hh * DH + d;
        float kvl = kraw[gi] * gate[gi];
        kvl = (kvl > 0.f) ? (kvl + 1.f) : expf(kvl);
        __half kh = __float2half_rn(kvl);
        Kt[d * 136 + t] = kh;
        kfp[t * DH + d] = kh;
        Vt[d * 136 + t] = vp[t * DH + d];
    }
    __syncthreads();

    uint32_t sb = smem_u32(sm2);
    uint32_t vtb = sb + 64 * 136 * 2;
    int lr = lane & 7, g = lane >> 3;
    int arow = ((g & 1) << 3) + lr;
    int acolb = (g >> 1) << 4;
    int brow = ((g >> 1) << 3) + lr;
    int bcolb = (g & 1) << 4;
    int wm = wid >> 2, wn = wid & 3;
    int m0 = wm * 32, n0 = wn * 16;

    float acc[2][2][4];
    #pragma unroll
    for (int mt = 0; mt < 2; mt++)
        #pragma unroll
        for (int nt = 0; nt < 2; nt++)
            #pragma unroll
            for (int q = 0; q < 4; q++) acc[mt][nt][q] = 0.f;

    #pragma unroll
    for (int kt = 0; kt < 8; kt++) {
        uint32_t bf[2][2];
        uint32_t baddr = vtb + (uint32_t)((n0 + brow) * 272 + kt * 32 + bcolb);
        LDSM4(bf[0][0], bf[0][1], bf[1][0], bf[1][1], baddr);
        #pragma unroll
        for (int mt = 0; mt < 2; mt++) {
            uint32_t aaddr = sb + (uint32_t)((m0 + mt * 16 + arow) * 272 + kt * 32 + acolb);
            uint32_t af[4];
            LDSM4(af[0], af[1], af[2], af[3], aaddr);
            #pragma unroll
            for (int nt = 0; nt < 2; nt++)
                MMA_F16(acc[mt][nt], af, bf[nt]);
        }
    }

    float* kvp = kv + (size_t)(bh * NC + c) * DH * DH;
    int r0 = lane >> 2, cpair = (lane & 3) << 1;
    #pragma unroll
    for (int mt = 0; mt < 2; mt++)
        #pragma unroll
        for (int nt = 0; nt < 2; nt++)
            #pragma unroll
            for (int h = 0; h < 2; h++) {
                int i = m0 + mt * 16 + r0 + 8 * h;
                int j = n0 + nt * 8 + cpair;
                *(float2*)(kvp + i * DH + j) =
                    make_float2(acc[mt][nt][2*h], acc[mt][nt][2*h + 1]);
            }
    if (tid < 64) {
        float s = 0.f;
        const __half2* kr = (const __half2*)(Kt + tid * 136);
        #pragma unroll
        for (int t = 0; t < 64; t++) {
            float2 f = __half22float2(kr[t]);
            s += f.x + f.y;
        }
        ksum[(bh * NC + c) * DH + tid] = s;
    }
}

// ---------------- exclusive prefix over chunks ----------------------------
__global__ void scan_kernel(const float* __restrict__ kv,
                            const float* __restrict__ ksum,
                            float* __restrict__ sprev,
                            float* __restrict__ ksp) {
    int bh = blockIdx.x;
    int tid = threadIdx.x;  // 256
    #pragma unroll
    for (int r = 0; r < 16; r++) {
        int e = tid + 256 * r;
        float acc = 0.f;
        #pragma unroll
        for (int c = 0; c < NC; c++) {
            size_t o = (size_t)(bh * NC + c) * DH * DH + e;
            sprev[o] = acc;
            acc += kv[o];
        }
    }
    if (tid < 64) {
        float acc = 0.f;
        #pragma unroll
        for (int c = 0; c < NC; c++) {
            size_t o = (size_t)(bh * NC + c) * DH + tid;
            ksp[o] = acc;
            acc += ksum[o];
        }
    }
}

// ---------------- per-chunk attention via MMA ------------------------------
// smem (halves): Q 128x72 @0 | K 128x72 @9216 | Vt 64x136 @18432 |
//                St 64x72 @27136 | Af 128x136 @31744 | floats @98304 (den128,ks64)
#define AQ   0
#define AK   9216
#define AVT  18432
#define AST  27136
#define AAF  31744
#define AFLB 98304
#define ATTN_SMEM_BYTES (AFLB + 768)

__global__ void __launch_bounds__(256) attn_kernel(
        const __half* __restrict__ qf,
        const __half* __restrict__ kf,
        const __half* __restrict__ vf,
        const float* __restrict__ sprev,
        const float* __restrict__ ksp,
        __half* __restrict__ ao16) {
    extern __shared__ __half smh[];
    float* flt = (float*)((char*)smh + AFLB);
    uint32_t sb = smem_u32(smh);
    int c = blockIdx.x, bh = blockIdx.y;
    int tid = threadIdx.x;   // 256
    int wid = tid >> 5, lane = tid & 31;
    const __half* qp = qf + (size_t)(bh * L2 + c * CHK) * DH;
    const __half* kp = kf + (size_t)(bh * L2 + c * CHK) * DH;
    const __half* vp = vf + (size_t)(bh * L2 + c * CHK) * DH;
    const float* sp  = sprev + (size_t)(bh * NC + c) * DH * DH;

    for (int i = tid; i < 1024; i += 256) {
        int row = i >> 3, seg = i & 7;
        *(uint4*)(smh + AQ + row * 72 + seg * 8) = *(const uint4*)(qp + row * DH + seg * 8);
        *(uint4*)(smh + AK + row * 72 + seg * 8) = *(const uint4*)(kp + row * DH + seg * 8);
    }
    for (int i = tid; i < CHK * DH; i += 256) {
        int t = i >> 6, j = i & 63;
        smh[AVT + j * 136 + t] = vp[t * DH + j];
    }
    for (int i = tid; i < DH * DH; i += 256) {
        int d = i >> 6, e = i & 63;
        smh[AST + e * 72 + d] = __float2half_rn(sp[d * DH + e]);
    }
    if (tid < 64) flt[128 + tid] = ksp[(bh * NC + c) * DH + tid];
    __syncthreads();

    int lr = lane & 7, g = lane >> 3;
    int arow = ((g & 1) << 3) + lr;
    int acolb = (g >> 1) << 4;
    int brow = ((g >> 1) << 3) + lr;
    int bcolb = (g & 1) << 4;
    int r0 = lane >> 2, cpair = (lane & 3) << 1;

    // ---- A = QK^T -> causal mask -> fp16 Af ----
    {
        int wm = wid >> 2, wn = wid & 3;
        int m0 = wm * 64, n0 = wn * 32;
        float qa[4][4][4];
        #pragma unroll
        for (int mt = 0; mt < 4; mt++)
            #pragma unroll
            for (int nt = 0; nt < 4; nt++)
                #pragma unroll
                for (int q = 0; q < 4; q++) qa[mt][nt][q] = 0.f;
        #pragma unroll
        for (int kt = 0; kt < 4; kt++) {
            uint32_t bf[4][2];
            #pragma unroll
            for (int t = 0; t < 2; t++) {
                uint32_t baddr = sb + AK * 2 + (uint32_t)((n0 + t * 16 + brow) * 144 + kt * 32 + bcolb);
                LDSM4(bf[2*t][0], bf[2*t][1], bf[2*t+1][0], bf[2*t+1][1], baddr);
            }
            #pragma unroll
            for (int mt = 0; mt < 4; mt++) {
                uint32_t aaddr = sb + AQ * 2 + (uint32_t)((m0 + mt * 16 + arow) * 144 + kt * 32 + acolb);
                uint32_t af[4];
                LDSM4(af[0], af[1], af[2], af[3], aaddr);
                #pragma unroll
                for (int nt = 0; nt < 4; nt++)
                    MMA_F16(qa[mt][nt], af, bf[nt]);
            }
        }
        #pragma unroll
        for (int mt = 0; mt < 4; mt++)
            #pragma unroll
            for (int nt = 0; nt < 4; nt++)
                #pragma unroll
                for (int h = 0; h < 2; h++) {
                    int ai = m0 + mt * 16 + r0 + 8 * h;
                    int aj = n0 + nt * 8 + cpair;
                    float v0 = (aj     <= ai) ? qa[mt][nt][2*h]     : 0.f;
                    float v1 = (aj + 1 <= ai) ? qa[mt][nt][2*h + 1] : 0.f;
                    *(__half2*)(smh + AAF + ai * 136 + aj) = __floats2half2_rn(v0, v1);
                }
    }
    __syncthreads();

    // ---- denominators ----
    if (tid < 128) {
        float s = 0.f;
        const __half2* ar = (const __half2*)(smh + AAF + tid * 136);
        #pragma unroll
        for (int jj = 0; jj < 64; jj++) {
            float2 f = __half22float2(ar[jj]);
            s += f.x + f.y;
        }
        const __half* qr = smh + AQ + tid * 72;
        float qk = 0.f;
        #pragma unroll
        for (int d = 0; d < 64; d++)
            qk += __half2float(qr[d]) * flt[128 + d];
        flt[tid] = s + qk + 1e-6f;
    }
    __syncthreads();

    // ---- O = Af@V + Q@S_prev; divide; write fp16 ----
    {
        int wm2 = wid >> 1, wn2 = wid & 1;
        int m0 = wm2 * 32, n0 = wn2 * 32;
        float oa[2][4][4];
        #pragma unroll
        for (int mt = 0; mt < 2; mt++)
            #pragma unroll
            for (int nt = 0; nt < 4; nt++)
                #pragma unroll
                for (int q = 0; q < 4; q++) oa[mt][nt][q] = 0.f;
        #pragma unroll
        for (int kt = 0; kt < 8; kt++) {
            uint32_t bf[4][2];
            #pragma unroll
            for (int t = 0; t < 2; t++) {
                uint32_t baddr = sb + AVT * 2 + (uint32_t)((n0 + t * 16 + brow) * 272 + kt * 32 + bcolb);
                LDSM4(bf[2*t][0], bf[2*t][1], bf[2*t+1][0], bf[2*t+1][1], baddr);
            }
            #pragma unroll
            for (int mt = 0; mt < 2; mt++) {
                uint32_t aaddr = sb + AAF * 2 + (uint32_t)((m0 + mt * 16 + arow) * 272 + kt * 32 + acolb);
                uint32_t af[4];
                LDSM4(af[0], af[1], af[2], af[3], aaddr);
                #pragma unroll
                for (int nt = 0; nt < 4; nt++)
                    MMA_F16(oa[mt][nt], af, bf[nt]);
            }
        }
        #pragma unroll
        for (int kt = 0; kt < 4; kt++) {
            uint32_t bf[4][2];
            #pragma unroll
            for (int t = 0; t < 2; t++) {
                uint32_t baddr = sb + AST * 2 + (uint32_t)((n0 + t * 16 + brow) * 144 + kt * 32 + bcolb);
                LDSM4(bf[2*t][0], bf[2*t][1], bf[2*t+1][0], bf[2*t+1][1], baddr);
            }
            #pragma unroll
            for (int mt = 0; mt < 2; mt++) {
                uint32_t aaddr = sb + AQ * 2 + (uint32_t)((m0 + mt * 16 + arow) * 144 + kt * 32 + acolb);
                uint32_t af[4];
                LDSM4(af[0], af[1], af[2], af[3], aaddr);
                #pragma unroll
                for (int nt = 0; nt < 4; nt++)
                    MMA_F16(oa[mt][nt], af, bf[nt]);
            }
        }
        int b = bh / H2, hh = bh - b * H2;
        #pragma unroll
        for (int mt = 0; mt < 2; mt++)
            #pragma unroll
            for (int nt = 0; nt < 4; nt++)
                #pragma unroll
                for (int h = 0; h < 2; h++) {
                    int oi = m0 + mt * 16 + r0 + 8 * h;
                    int oj = n0 + nt * 8 + cpair;
                    float dv = flt[oi];
                    float w0 = oa[mt][nt][2*h]     / dv;
                    float w1 = oa[mt][nt][2*h + 1] / dv;
                    int l = c * CHK + oi;
                    *(__half2*)(ao16 + (size_t)(b * L2 + l) * D2 + hh * DH + oj) =
                        __floats2half2_rn(w0, w1);
                }
    }
}

// ---------------- launch ---------------------------------------------------
extern "C" void kernel_launch(void* const* d_in, const int* in_sizes, int n_in,
                              void* d_out, int out_size) {
    const float* x      = (const float*)d_in[0];
    const float* W_qkv  = (const float*)d_in[1];
    const float* b_qkv  = (const float*)d_in[2];
    const float* W_gate = (const float*)d_in[3];
    const float* b_gate = (const float*)d_in[4];
    const float* W_proj = (const float*)d_in[5];
    const float* b_proj = (const float*)d_in[6];
    const float* ln_g   = (const float*)d_in[7];
    const float* ln_b   = (const float*)d_in[8];
    float* out  = (float*)d_out;           // proj output
    float* gate = out + OUT_ELEMS;         // gate output (2nd return value)

    float *p_kraw, *p_kv, *p_ksum, *p_sprev, *p_ksp;
    __half *p_an, *p_x16, *p_at16, *p_wtq, *p_wtg, *p_wtp;
    __half *p_qf16, *p_kf16, *p_vf16;
    cudaGetSymbolAddress((void**)&p_kraw,  g_kraw);
    cudaGetSymbolAddress((void**)&p_kv,    g_kv);
    cudaGetSymbolAddress((void**)&p_ksum,  g_ksum);
    cudaGetSymbolAddress((void**)&p_sprev, g_sprev);
    cudaGetSymbolAddress((void**)&p_ksp,   g_ksp);
    cudaGetSymbolAddress((void**)&p_an,    g_an);
    cudaGetSymbolAddress((void**)&p_x16,   g_x16);
    cudaGetSymbolAddress((void**)&p_at16,  g_at16);
    cudaGetSymbolAddress((void**)&p_wtq,   g_wtq);
    cudaGetSymbolAddress((void**)&p_wtg,   g_wtg);
    cudaGetSymbolAddress((void**)&p_wtp,   g_wtp);
    cudaGetSymbolAddress((void**)&p_qf16,  g_qf16);
    cudaGetSymbolAddress((void**)&p_kf16,  g_kf16);
    cudaGetSymbolAddress((void**)&p_vf16,  g_vf16);

    cudaFuncSetAttribute(gemm_qkv_gate, cudaFuncAttributeMaxDynamicSharedMemorySize,
                         GEMM_SMEM_BYTES);
    cudaFuncSetAttribute(gemm_proj, cudaFuncAttributeMaxDynamicSharedMemorySize,
                         GEMM_SMEM_BYTES);
    cudaFuncSetAttribute(attn_kernel, cudaFuncAttributeMaxDynamicSharedMemorySize,
                         ATTN_SMEM_BYTES);

    // 0. fused: weight transposes + LayerNorm (one launch)
    lt_kernel<<<NTRB + BL, 256>>>(W_qkv, W_gate, W_proj, p_wtq, p_wtg, p_wtp,
                                  x, ln_g, ln_b, p_an, p_x16);

    // 1. fused QKV + gate GEMM (q,v finished in epilogue; k -> fp32 kraw)
    gemm_qkv_gate<<<dim3(N3D / 128 + D2 / 128, BL / 128), 256, GEMM_SMEM_BYTES>>>(
        p_an, p_wtq, b_qkv, p_qf16, p_vf16, p_kraw,
        p_x16, p_wtg, b_gate, gate);

    // 2. per-chunk: gate+elu+1 on k, K^T V via MMA, kf16 out
    chunk_kv_kernel<<<dim3(NC, BH), 256>>>(p_kraw, gate, p_vf16, p_kf16, p_kv, p_ksum);

    // 3. exclusive prefix over chunks
    scan_kernel<<<BH, 256>>>(p_kv, p_ksum, p_sprev, p_ksp);

    // 4. per-chunk attention via MMA
    attn_kernel<<<dim3(NC, BH), 256, ATTN_SMEM_BYTES>>>(
        p_qf16, p_kf16, p_vf16, p_sprev, p_ksp, p_at16);

    // 5. out = attn @ W_proj + b_proj
    gemm_proj<<<dim3(D2 / 128, BL / 128), 256, GEMM_SMEM_BYTES>>>(
        p_at16, p_wtp, b_proj, out);
}

// round 13
// speedup vs baseline: 1.0424x; 1.0424x over previous
#include <cuda_runtime.h>
#include <cuda_fp16.h>
#include <math.h>
#include <stdint.h>

// Problem constants
#define B2   2
#define L2   1024
#define D2   768
#define H2   12
#define DH   64
#define BH   (B2*H2)        // 24
#define BL   (B2*L2)        // 2048
#define N3D  (3*D2)         // 2304
#define CHK  128            // chunk length
#define NC   (L2/CHK)       // 8
#define GK   768            // shared K dim of all GEMMs
#define OUT_ELEMS (BL*D2)   // 1572864

// ---------------- scratch (device globals; no allocation allowed) ----------
__device__ float g_kraw[BL*D2];      // k section fp32 (pre-gate)
__device__ float g_kv[BH*NC*DH*DH];
__device__ float g_ksum[BH*NC*DH];
__device__ float g_sprev[BH*NC*DH*DH];
__device__ float g_ksp[BH*NC*DH];
// fp16 operands (16B-aligned for cp.async / vector loads)
__device__ __align__(256) __half g_an[BL*GK];       // LN(x) fp16
__device__ __align__(256) __half g_x16[BL*GK];      // raw x fp16
__device__ __align__(256) __half g_at16[BL*D2];     // attn out fp16
__device__ __align__(256) __half g_qf16[BH*L2*DH];
__device__ __align__(256) __half g_kf16[BH*L2*DH];
__device__ __align__(256) __half g_vf16[BH*L2*DH];
__device__ __align__(256) __half g_wtq[N3D*GK];     // W_qkv^T fp16
__device__ __align__(256) __half g_wtg[D2*GK];      // W_gate^T fp16
__device__ __align__(256) __half g_wtp[D2*GK];      // W_proj^T fp16

// =================== helpers ===============================================
__device__ __forceinline__ uint32_t smem_u32(const void* p) {
    uint32_t a;
    asm("{ .reg .u64 t; cvta.to.shared.u64 t, %1; cvt.u32.u64 %0, t; }"
        : "=r"(a) : "l"(p));
    return a;
}
__device__ __forceinline__ uint32_t sw128(uint32_t off) {
    return off ^ ((off >> 3) & 0x70);
}

#define LDSM4(r0, r1, r2, r3, addr) \
    asm volatile("ldmatrix.sync.aligned.m8n8.x4.shared.b16 {%0,%1,%2,%3}, [%4];" \
        : "=r"(r0), "=r"(r1), "=r"(r2), "=r"(r3) : "r"(addr))

#define MMA_F16(d, a, b) \
    asm volatile("mma.sync.aligned.m16n8k16.row.col.f32.f16.f16.f32 " \
        "{%0,%1,%2,%3},{%4,%5,%6,%7},{%8,%9},{%0,%1,%2,%3};" \
        : "+f"((d)[0]), "+f"((d)[1]), "+f"((d)[2]), "+f"((d)[3]) \
        : "r"((a)[0]), "r"((a)[1]), "r"((a)[2]), "r"((a)[3]), \
          "r"((b)[0]), "r"((b)[1]))

#define CP_ASYNC16(dst, src) \
    asm volatile("cp.async.cg.shared.global [%0], [%1], 16;" \
        :: "r"((uint32_t)(dst)), "l"(src))
#define CP_COMMIT() asm volatile("cp.async.commit_group;" ::: "memory")
#define CP_WAIT(n)  asm volatile("cp.async.wait_group %0;" :: "n"(n) : "memory")

// ------- fused: weight transposes + LayerNorm ------------------------------
// grid.x: [0, 2880) transpose tiles; [2880, 4928) ln rows. 256 threads.
#define NTRB ((N3D + D2 + D2) / 32 * (GK / 32))   // 120*24 = 2880

__global__ void lt_kernel(const float* __restrict__ Wq,
                          const float* __restrict__ Wg,
                          const float* __restrict__ Wp,
                          __half* __restrict__ wtq,
                          __half* __restrict__ wtg,
                          __half* __restrict__ wtp,
                          const float* __restrict__ x,
                          const float* __restrict__ lg,
                          const float* __restrict__ lb,
                          __half* __restrict__ an, __half* __restrict__ x16) {
    __shared__ float t[32][33];
    __shared__ float ss[6], sqs[6];
    int bid = blockIdx.x;
    int tid = threadIdx.x;
    if (bid < NTRB) {
        // ---- transpose tile ----
        int bx = bid % 120;
        int k0 = (bid / 120) * 32;
        const float* W; __half* Wt; int N;
        if (bx < N3D / 32)                { W = Wq; Wt = wtq; N = N3D; }
        else if (bx < N3D / 32 + D2 / 32) { W = Wg; Wt = wtg; N = D2; bx -= N3D / 32; }
        else                              { W = Wp; Wt = wtp; N = D2; bx -= N3D / 32 + D2 / 32; }
        int n0 = bx * 32;
        int tx = tid & 31, ty = tid >> 5;   // 32 x 8
        #pragma unroll
        for (int r = ty; r < 32; r += 8)
            t[r][tx] = W[(size_t)(k0 + r) * N + n0 + tx];
        __syncthreads();
        #pragma unroll
        for (int r = ty; r < 32; r += 8)
            Wt[(size_t)(n0 + r) * GK + k0 + tx] = __float2half_rn(t[tx][r]);
    } else {
        // ---- layernorm row ----
        int row = bid - NTRB;
        float4 v = make_float4(0.f, 0.f, 0.f, 0.f);
        if (tid < 192) v = ((const float4*)(x + (size_t)row * D2))[tid];
        float s  = v.x + v.y + v.z + v.w;
        float sq = v.x*v.x + v.y*v.y + v.z*v.z + v.w*v.w;
        #pragma unroll
        for (int o = 16; o; o >>= 1) {
            s  += __shfl_xor_sync(0xffffffffu, s,  o);
            sq += __shfl_xor_sync(0xffffffffu, sq, o);
        }
        if (tid < 192 && (tid & 31) == 0) { ss[tid >> 5] = s; sqs[tid >> 5] = sq; }
        __syncthreads();
        float ts = 0.f, tq = 0.f;
        #pragma unroll
        for (int w = 0; w < 6; w++) { ts += ss[w]; tq += sqs[w]; }
        float mean = ts * (1.f / D2);
        float var  = tq * (1.f / D2) - mean * mean;
        float inv  = rsqrtf(var + 1e-5f);
        if (tid < 192) {
            int cc = tid * 4;
            float4 gg = ((const float4*)lg)[tid];
            float4 bb = ((const float4*)lb)[tid];
            float n0 = (v.x - mean) * inv * gg.x + bb.x;
            float n1 = (v.y - mean) * inv * gg.y + bb.y;
            float n2 = (v.z - mean) * inv * gg.z + bb.z;
            float n3 = (v.w - mean) * inv * gg.w + bb.w;
            __half2 a01 = __floats2half2_rn(n0, n1);
            __half2 a23 = __floats2half2_rn(n2, n3);
            *(uint2*)(an + (size_t)row * D2 + cc) =
                make_uint2(*(uint32_t*)&a01, *(uint32_t*)&a23);
            __half2 x01 = __floats2half2_rn(v.x, v.y);
            __half2 x23 = __floats2half2_rn(v.z, v.w);
            *(uint2*)(x16 + (size_t)row * D2 + cc) =
                make_uint2(*(uint32_t*)&x01, *(uint32_t*)&x23);
        }
    }
}

// ---------------- fp16 mma.sync GEMM, 2-stage cp.async ---------------------
// EPI: 0 = plain fp32 C, 1 = sigmoid fp32 C, 2 = fused qkv epilogue
#define BKC 64
#define STG_A 0
#define STG_B 16384
#define STAGE_B 32768
#define NSTG 2
#define GEMM_SMEM_BYTES (NSTG * STAGE_B)   // 65536
#define NCHUNK (GK / BKC)   // 12

template <int EPI>
__device__ __forceinline__ void gemm_core(char* smem,
    const __half* __restrict__ Ap, const __half* __restrict__ Bp,
    const float* __restrict__ bias, float* __restrict__ C,
    int Nld, int cb0, int rb0,
    __half* __restrict__ qf, __half* __restrict__ vf,
    float* __restrict__ kraw)
{
    uint32_t sb = smem_u32(smem);
    int tid  = threadIdx.x;
    int wid  = tid >> 5, lane = tid & 31;
    int wm   = wid >> 2, wn = wid & 3;        // warp grid 2x4
    int m0   = wm * 64;
    int n0   = wn * 32;
    int lr   = lane & 7, g = lane >> 3;
    int arow = ((g & 1) << 3) + lr;
    int acolb = (g >> 1) << 4;
    int brow = ((g >> 1) << 3) + lr;
    int bcolb = (g & 1) << 4;

    int srow[4], sseg[4]; uint32_t soff[4];
    #pragma unroll
    for (int i = 0; i < 4; i++) {
        int idx = tid + 256 * i;
        srow[i] = idx >> 3;
        sseg[i] = idx & 7;
        soff[i] = sw128((uint32_t)(srow[i] * 128 + sseg[i] * 16));
    }

    float acc[4][4][4];
    #pragma unroll
    for (int mt = 0; mt < 4; mt++)
        #pragma unroll
        for (int nt = 0; nt < 4; nt++)
            #pragma unroll
            for (int q = 0; q < 4; q++) acc[mt][nt][q] = 0.f;

    {
        uint32_t db = sb;
        #pragma unroll
        for (int i = 0; i < 4; i++) {
            size_t off = (size_t)srow[i] * GK + sseg[i] * 8;
            CP_ASYNC16(db + STG_A + soff[i], Ap + off);
            CP_ASYNC16(db + STG_B + soff[i], Bp + off);
        }
        CP_COMMIT();
    }

    for (int c = 0; c < NCHUNK; c++) {
        int st = c & 1;
        CP_WAIT(0);
        __syncthreads();
        if (c + 1 < NCHUNK) {
            uint32_t db = sb + (st ^ 1) * STAGE_B;
            int k0 = (c + 1) * BKC;
            #pragma unroll
            for (int i = 0; i < 4; i++) {
                size_t off = (size_t)srow[i] * GK + k0 + sseg[i] * 8;
                CP_ASYNC16(db + STG_A + soff[i], Ap + off);
                CP_ASYNC16(db + STG_B + soff[i], Bp + off);
            }
            CP_COMMIT();
        }

        uint32_t sA = sb + st * STAGE_B;
        uint32_t sB = sA + STG_B;
        #pragma unroll
        for (int kt = 0; kt < 4; kt++) {
            uint32_t bf[4][2];
            #pragma unroll
            for (int t = 0; t < 2; t++) {
                uint32_t boff = sw128((uint32_t)((n0 + t * 16 + brow) * 128 + kt * 32 + bcolb));
                LDSM4(bf[2*t][0], bf[2*t][1], bf[2*t+1][0], bf[2*t+1][1], sB + boff);
            }
            #pragma unroll
            for (int mt = 0; mt < 4; mt++) {
                uint32_t aoff = sw128((uint32_t)((m0 + mt * 16 + arow) * 128 + kt * 32 + acolb));
                uint32_t af[4];
                LDSM4(af[0], af[1], af[2], af[3], sA + aoff);
                #pragma unroll
                for (int nt = 0; nt < 4; nt++)
                    MMA_F16(acc[mt][nt], af, bf[nt]);
            }
        }
        __syncthreads();
    }

    int rbase = rb0 + m0 + (lane >> 2);
    int cbase = cb0 + n0 + ((lane & 3) << 1);
    if (EPI < 2) {
        #pragma unroll
        for (int mt = 0; mt < 4; mt++) {
            #pragma unroll
            for (int nt = 0; nt < 4; nt++) {
                int col = cbase + nt * 8;
                float b0 = bias[col], b1 = bias[col + 1];
                #pragma unroll
                for (int h = 0; h < 2; h++) {
                    int row = rbase + mt * 16 + h * 8;
                    float o0 = acc[mt][nt][2*h + 0] + b0;
                    float o1 = acc[mt][nt][2*h + 1] + b1;
                    if (EPI == 1) {
                        o0 = 1.f / (1.f + expf(-o0));
                        o1 = 1.f / (1.f + expf(-o1));
                    }
                    *(float2*)(C + (size_t)row * Nld + col) = make_float2(o0, o1);
                }
            }
        }
    } else {
        // qkv epilogue: q -> elu+1 fp16 head layout; v -> fp16 head layout;
        //               k -> fp32 kraw (gate applied later inside chunk_kv)
        int sec = cb0 / D2;      // 0=q, 1=k, 2=v (tile never straddles sections)
        if (sec == 1) {
            #pragma unroll
            for (int mt = 0; mt < 4; mt++) {
                #pragma unroll
                for (int nt = 0; nt < 4; nt++) {
                    int col = cbase + nt * 8;
                    int cc  = col - D2;
                    float b0 = bias[col], b1 = bias[col + 1];
                    #pragma unroll
                    for (int h = 0; h < 2; h++) {
                        int row = rbase + mt * 16 + h * 8;
                        float o0 = acc[mt][nt][2*h + 0] + b0;
                        float o1 = acc[mt][nt][2*h + 1] + b1;
                        *(float2*)(kraw + (size_t)row * D2 + cc) = make_float2(o0, o1);
                    }
                }
            }
        } else {
            __half* dst = (sec == 0) ? qf : vf;
            #pragma unroll
            for (int mt = 0; mt < 4; mt++) {
                #pragma unroll
                for (int nt = 0; nt < 4; nt++) {
                    int col = cbase + nt * 8;
                    int cc  = col - sec * D2;
                    int hh = cc >> 6, d = cc & 63;
                    float b0 = bias[col], b1 = bias[col + 1];
                    #pragma unroll
                    for (int h = 0; h < 2; h++) {
                        int row = rbase + mt * 16 + h * 8;
                        float o0 = acc[mt][nt][2*h + 0] + b0;
                        float o1 = acc[mt][nt][2*h + 1] + b1;
                        if (sec == 0) {
                            o0 = (o0 > 0.f) ? (o0 + 1.f) : expf(o0);
                            o1 = (o1 > 0.f) ? (o1 + 1.f) : expf(o1);
                        }
                        int b = row >> 10, l = row & 1023;
                        size_t o = ((size_t)(b * H2 + hh) * L2 + l) * DH + d;
                        *(__half2*)(dst + o) = __floats2half2_rn(o0, o1);
                    }
                }
            }
        }
    }
}

// fused QKV + gate GEMM: bx<18 -> QKV tile (fused epilogue), bx>=18 -> gate
__global__ void __launch_bounds__(256, 2) gemm_qkv_gate(
    const __half* __restrict__ xn,  const __half* __restrict__ wq,
    const float* __restrict__ bq,
    __half* __restrict__ qf, __half* __restrict__ vf, float* __restrict__ kraw,
    const __half* __restrict__ x16, const __half* __restrict__ wg,
    const float* __restrict__ bg,   float* __restrict__ gateC)
{
    extern __shared__ char smem[];
    int bx = blockIdx.x, by = blockIdx.y;
    if (bx < N3D / 128) {
        gemm_core<2>(smem, xn + (size_t)by * 128 * GK,
                     wq + (size_t)bx * 128 * GK, bq, nullptr, 0,
                     bx * 128, by * 128, qf, vf, kraw);
    } else {
        int b2 = bx - N3D / 128;
        gemm_core<1>(smem, x16 + (size_t)by * 128 * GK,
                     wg + (size_t)b2 * 128 * GK, bg, gateC, D2,
                     b2 * 128, by * 128, nullptr, nullptr, nullptr);
    }
}

__global__ void __launch_bounds__(256, 2) gemm_proj(
    const __half* __restrict__ at16, const __half* __restrict__ wp,
    const float* __restrict__ bp,    float* __restrict__ outC)
{
    extern __shared__ char smem[];
    gemm_core<0>(smem, at16 + (size_t)blockIdx.y * 128 * GK,
                 wp + (size_t)blockIdx.x * 128 * GK, bp, outC, D2,
                 blockIdx.x * 128, blockIdx.y * 128, nullptr, nullptr, nullptr);
}

// --------- per-chunk: fused kprep + K^T V via MMA + ksum + kf16 ------------
__global__ void chunk_kv_kernel(const float* __restrict__ kraw,
                                const float* __restrict__ gate,
                                const __half* __restrict__ vf,
                                __half* __restrict__ kf,
                                float* __restrict__ kv,
                                float* __restrict__ ksum) {
    __shared__ __half sm2[2 * 64 * 136];
    __half* Kt = sm2;
    __half* Vt = sm2 + 64 * 136;
    int c = blockIdx.x, bh = blockIdx.y;
    int bb = bh / H2, hh = bh - bb * H2;
    int tid = threadIdx.x;   // 256
    int wid = tid >> 5, lane = tid & 31;
    const __half* vp = vf + (size_t)(bh * L2 + c * CHK) * DH;
    size_t blbase = (size_t)(bb * L2 + c * CHK);
    __half* kfp = kf + (size_t)(bh * L2 + c * CHK) * DH;
    for (int i = tid; i < CHK * DH; i += 256) {
        int t = i >> 6, d = i & 63;
        size_t gi = (blbase + t) * D2 + hh * DH + d;
        float kvl = kraw[gi] * gate[gi];
        kvl = (kvl > 0.f) ? (kvl + 1.f) : expf(kvl);
        __half kh = __float2half_rn(kvl);
        Kt[d * 136 + t] = kh;
        kfp[t * DH + d] = kh;
        Vt[d * 136 + t] = vp[t * DH + d];
    }
    __syncthreads();

    uint32_t sb = smem_u32(sm2);
    uint32_t vtb = sb + 64 * 136 * 2;
    int lr = lane & 7, g = lane >> 3;
    int arow = ((g & 1) << 3) + lr;
    int acolb = (g >> 1) << 4;
    int brow = ((g >> 1) << 3) + lr;
    int bcolb = (g & 1) << 4;
    int wm = wid >> 2, wn = wid & 3;
    int m0 = wm * 32, n0 = wn * 16;

    float acc[2][2][4];
    #pragma unroll
    for (int mt = 0; mt < 2; mt++)
        #pragma unroll
        for (int nt = 0; nt < 2; nt++)
            #pragma unroll
            for (int q = 0; q < 4; q++) acc[mt][nt][q] = 0.f;

    #pragma unroll
    for (int kt = 0; kt < 8; kt++) {
        uint32_t bf[2][2];
        uint32_t baddr = vtb + (uint32_t)((n0 + brow) * 272 + kt * 32 + bcolb);
        LDSM4(bf[0][0], bf[0][1], bf[1][0], bf[1][1], baddr);
        #pragma unroll
        for (int mt = 0; mt < 2; mt++) {
            uint32_t aaddr = sb + (uint32_t)((m0 + mt * 16 + arow) * 272 + kt * 32 + acolb);
            uint32_t af[4];
            LDSM4(af[0], af[1], af[2], af[3], aaddr);
            #pragma unroll
            for (int nt = 0; nt < 2; nt++)
                MMA_F16(acc[mt][nt], af, bf[nt]);
        }
    }

    float* kvp = kv + (size_t)(bh * NC + c) * DH * DH;
    int r0 = lane >> 2, cpair = (lane & 3) << 1;
    #pragma unroll
    for (int mt = 0; mt < 2; mt++)
        #pragma unroll
        for (int nt = 0; nt < 2; nt++)
            #pragma unroll
            for (int h = 0; h < 2; h++) {
                int i = m0 + mt * 16 + r0 + 8 * h;
                int j = n0 + nt * 8 + cpair;
                *(float2*)(kvp + i * DH + j) =
                    make_float2(acc[mt][nt][2*h], acc[mt][nt][2*h + 1]);
            }
    if (tid < 64) {
        float s = 0.f;
        const __half2* kr = (const __half2*)(Kt + tid * 136);
        #pragma unroll
        for (int t = 0; t < 64; t++) {
            float2 f = __half22float2(kr[t]);
            s += f.x + f.y;
        }
        ksum[(bh * NC + c) * DH + tid] = s;
    }
}

// ------ exclusive prefix over chunks: one thread per element chain ---------
// grid: 390 blocks x 256 = 99840 threads; [0, 98304) matrix, rest ksum
__global__ void scan_kernel(const float* __restrict__ kv,
                            const float* __restrict__ ksum,
                            float* __restrict__ sprev,
                            float* __restrict__ ksp) {
    int i = blockIdx.x * 256 + threadIdx.x;
    if (i < BH * DH * DH) {
        int bh = i >> 12;
        int e  = i & 4095;
        float acc = 0.f;
        #pragma unroll
        for (int c = 0; c < NC; c++) {
            size_t o = (size_t)(bh * NC + c) * (DH * DH) + e;
            sprev[o] = acc;
            acc += kv[o];
        }
    } else {
        int j = i - BH * DH * DH;    // 0..1535
        int bh = j >> 6;
        int e  = j & 63;
        float acc = 0.f;
        #pragma unroll
        for (int c = 0; c < NC; c++) {
            size_t o = (size_t)(bh * NC + c) * DH + e;
            ksp[o] = acc;
            acc += ksum[o];
        }
    }
}

// ---------------- per-chunk attention via MMA ------------------------------
// smem (halves): Q 128x72 @0 | K 128x72 @9216 | Vt 64x136 @18432 |
//                St 64x72 @27136 | Af 128x136 @31744 | floats @98304 (den128,ks64)
#define AQ   0
#define AK   9216
#define AVT  18432
#define AST  27136
#define AAF  31744
#define AFLB 98304
#define ATTN_SMEM_BYTES (AFLB + 768)

__global__ void __launch_bounds__(256) attn_kernel(
        const __half* __restrict__ qf,
        const __half* __restrict__ kf,
        const __half* __restrict__ vf,
        const float* __restrict__ sprev,
        const float* __restrict__ ksp,
        __half* __restrict__ ao16) {
    extern __shared__ __half smh[];
    float* flt = (float*)((char*)smh + AFLB);
    uint32_t sb = smem_u32(smh);
    int c = blockIdx.x, bh = blockIdx.y;
    int tid = threadIdx.x;   // 256
    int wid = tid >> 5, lane = tid & 31;
    const __half* qp = qf + (size_t)(bh * L2 + c * CHK) * DH;
    const __half* kp = kf + (size_t)(bh * L2 + c * CHK) * DH;
    const __half* vp = vf + (size_t)(bh * L2 + c * CHK) * DH;
    const float* sp  = sprev + (size_t)(bh * NC + c) * DH * DH;

    for (int i = tid; i < 1024; i += 256) {
        int row = i >> 3, seg = i & 7;
        *(uint4*)(smh + AQ + row * 72 + seg * 8) = *(const uint4*)(qp + row * DH + seg * 8);
        *(uint4*)(smh + AK + row * 72 + seg * 8) = *(const uint4*)(kp + row * DH + seg * 8);
    }
    for (int i = tid; i < CHK * DH; i += 256) {
        int t = i >> 6, j = i & 63;
        smh[AVT + j * 136 + t] = vp[t * DH + j];
    }
    for (int i = tid; i < DH * DH; i += 256) {
        int d = i >> 6, e = i & 63;
        smh[AST + e * 72 + d] = __float2half_rn(sp[d * DH + e]);
    }
    if (tid < 64) flt[128 + tid] = ksp[(bh * NC + c) * DH + tid];
    __syncthreads();

    int lr = lane & 7, g = lane >> 3;
    int arow = ((g & 1) << 3) + lr;
    int acolb = (g >> 1) << 4;
    int brow = ((g >> 1) << 3) + lr;
    int bcolb = (g & 1) << 4;
    int r0 = lane >> 2, cpair = (lane & 3) << 1;

    // ---- A = QK^T -> causal mask -> fp16 Af ----
    {
        int wm = wid >> 2, wn = wid & 3;
        int m0 = wm * 64, n0 = wn * 32;
        float qa[4][4][4];
        #pragma unroll
        for (int mt = 0; mt < 4; mt++)
            #pragma unroll
            for (int nt = 0; nt < 4; nt++)
                #pragma unroll
                for (int q = 0; q < 4; q++) qa[mt][nt][q] = 0.f;
        #pragma unroll
        for (int kt = 0; kt < 4; kt++) {
            uint32_t bf[4][2];
            #pragma unroll
            for (int t = 0; t < 2; t++) {
                uint32_t baddr = sb + AK * 2 + (uint32_t)((n0 + t * 16 + brow) * 144 + kt * 32 + bcolb);
                LDSM4(bf[2*t][0], bf[2*t][1], bf[2*t+1][0], bf[2*t+1][1], baddr);
            }
            #pragma unroll
            for (int mt = 0; mt < 4; mt++) {
                uint32_t aaddr = sb + AQ * 2 + (uint32_t)((m0 + mt * 16 + arow) * 144 + kt * 32 + acolb);
                uint32_t af[4];
                LDSM4(af[0], af[1], af[2], af[3], aaddr);
                #pragma unroll
                for (int nt = 0; nt < 4; nt++)
                    MMA_F16(qa[mt][nt], af, bf[nt]);
            }
        }
        #pragma unroll
        for (int mt = 0; mt < 4; mt++)
            #pragma unroll
            for (int nt = 0; nt < 4; nt++)
                #pragma unroll
                for (int h = 0; h < 2; h++) {
                    int ai = m0 + mt * 16 + r0 + 8 * h;
                    int aj = n0 + nt * 8 + cpair;
                    float v0 = (aj     <= ai) ? qa[mt][nt][2*h]     : 0.f;
                    float v1 = (aj + 1 <= ai) ? qa[mt][nt][2*h + 1] : 0.f;
                    *(__half2*)(smh + AAF + ai * 136 + aj) = __floats2half2_rn(v0, v1);
                }
    }
    __syncthreads();

    // ---- denominators ----
    if (tid < 128) {
        float s = 0.f;
        const __half2* ar = (const __half2*)(smh + AAF + tid * 136);
        #pragma unroll
        for (int jj = 0; jj < 64; jj++) {
            float2 f = __half22float2(ar[jj]);
            s += f.x + f.y;
        }
        const __half* qr = smh + AQ + tid * 72;
        float qk = 0.f;
        #pragma unroll
        for (int d = 0; d < 64; d++)
            qk += __half2float(qr[d]) * flt[128 + d];
        flt[tid] = s + qk + 1e-6f;
    }
    __syncthreads();

    // ---- O = Af@V + Q@S_prev; divide; write fp16 ----
    {
        int wm2 = wid >> 1, wn2 = wid & 1;
        int m0 = wm2 * 32, n0 = wn2 * 32;
        float oa[2][4][4];
        #pragma unroll
        for (int mt = 0; mt < 2; mt++)
            #pragma unroll
            for (int nt = 0; nt < 4; nt++)
                #pragma unroll
                for (int q = 0; q < 4; q++) oa[mt][nt][q] = 0.f;
        #pragma unroll
        for (int kt = 0; kt < 8; kt++) {
            uint32_t bf[4][2];
            #pragma unroll
            for (int t = 0; t < 2; t++) {
                uint32_t baddr = sb + AVT * 2 + (uint32_t)((n0 + t * 16 + brow) * 272 + kt * 32 + bcolb);
                LDSM4(bf[2*t][0], bf[2*t][1], bf[2*t+1][0], bf[2*t+1][1], baddr);
            }
            #pragma unroll
            for (int mt = 0; mt < 2; mt++) {
                uint32_t aaddr = sb + AAF * 2 + (uint32_t)((m0 + mt * 16 + arow) * 272 + kt * 32 + acolb);
                uint32_t af[4];
                LDSM4(af[0], af[1], af[2], af[3], aaddr);
                #pragma unroll
                for (int nt = 0; nt < 4; nt++)
                    MMA_F16(oa[mt][nt], af, bf[nt]);
            }
        }
        #pragma unroll
        for (int kt = 0; kt < 4; kt++) {
            uint32_t bf[4][2];
            #pragma unroll
            for (int t = 0; t < 2; t++) {
                uint32_t baddr = sb + AST * 2 + (uint32_t)((n0 + t * 16 + brow) * 144 + kt * 32 + bcolb);
                LDSM4(bf[2*t][0], bf[2*t][1], bf[2*t+1][0], bf[2*t+1][1], baddr);
            }
            #pragma unroll
            for (int mt = 0; mt < 2; mt++) {
                uint32_t aaddr = sb + AQ * 2 + (uint32_t)((m0 + mt * 16 + arow) * 144 + kt * 32 + acolb);
                uint32_t af[4];
                LDSM4(af[0], af[1], af[2], af[3], aaddr);
                #pragma unroll
                for (int nt = 0; nt < 4; nt++)
                    MMA_F16(oa[mt][nt], af, bf[nt]);
            }
        }
        int b = bh / H2, hh = bh - b * H2;
        #pragma unroll
        for (int mt = 0; mt < 2; mt++)
            #pragma unroll
            for (int nt = 0; nt < 4; nt++)
                #pragma unroll
                for (int h = 0; h < 2; h++) {
                    int oi = m0 + mt * 16 + r0 + 8 * h;
                    int oj = n0 + nt * 8 + cpair;
                    float dv = flt[oi];
                    float w0 = oa[mt][nt][2*h]     / dv;
                    float w1 = oa[mt][nt][2*h + 1] / dv;
                    int l = c * CHK + oi;
                    *(__half2*)(ao16 + (size_t)(b * L2 + l) * D2 + hh * DH + oj) =
                        __floats2half2_rn(w0, w1);
                }
    }
}

// ---------------- launch ---------------------------------------------------
extern "C" void kernel_launch(void* const* d_in, const int* in_sizes, int n_in,
                              void* d_out, int out_size) {
    const float* x      = (const float*)d_in[0];
    const float* W_qkv  = (const float*)d_in[1];
    const float* b_qkv  = (const float*)d_in[2];
    const float* W_gate = (const float*)d_in[3];
    const float* b_gate = (const float*)d_in[4];
    const float* W_proj = (const float*)d_in[5];
    const float* b_proj = (const float*)d_in[6];
    const float* ln_g   = (const float*)d_in[7];
    const float* ln_b   = (const float*)d_in[8];
    float* out  = (float*)d_out;           // proj output
    float* gate = out + OUT_ELEMS;         // gate output (2nd return value)

    float *p_kraw, *p_kv, *p_ksum, *p_sprev, *p_ksp;
    __half *p_an, *p_x16, *p_at16, *p_wtq, *p_wtg, *p_wtp;
    __half *p_qf16, *p_kf16, *p_vf16;
    cudaGetSymbolAddress((void**)&p_kraw,  g_kraw);
    cudaGetSymbolAddress((void**)&p_kv,    g_kv);
    cudaGetSymbolAddress((void**)&p_ksum,  g_ksum);
    cudaGetSymbolAddress((void**)&p_sprev, g_sprev);
    cudaGetSymbolAddress((void**)&p_ksp,   g_ksp);
    cudaGetSymbolAddress((void**)&p_an,    g_an);
    cudaGetSymbolAddress((void**)&p_x16,   g_x16);
    cudaGetSymbolAddress((void**)&p_at16,  g_at16);
    cudaGetSymbolAddress((void**)&p_wtq,   g_wtq);
    cudaGetSymbolAddress((void**)&p_wtg,   g_wtg);
    cudaGetSymbolAddress((void**)&p_wtp,   g_wtp);
    cudaGetSymbolAddress((void**)&p_qf16,  g_qf16);
    cudaGetSymbolAddress((void**)&p_kf16,  g_kf16);
    cudaGetSymbolAddress((void**)&p_vf16,  g_vf16);

    cudaFuncSetAttribute(gemm_qkv_gate, cudaFuncAttributeMaxDynamicSharedMemorySize,
                         GEMM_SMEM_BYTES);
    cudaFuncSetAttribute(gemm_proj, cudaFuncAttributeMaxDynamicSharedMemorySize,
                         GEMM_SMEM_BYTES);
    cudaFuncSetAttribute(attn_kernel, cudaFuncAttributeMaxDynamicSharedMemorySize,
                         ATTN_SMEM_BYTES);

    // 0. fused: weight transposes + LayerNorm (one launch)
    lt_kernel<<<NTRB + BL, 256>>>(W_qkv, W_gate, W_proj, p_wtq, p_wtg, p_wtp,
                                  x, ln_g, ln_b, p_an, p_x16);

    // 1. fused QKV + gate GEMM (q,v finished in epilogue; k -> fp32 kraw)
    gemm_qkv_gate<<<dim3(N3D / 128 + D2 / 128, BL / 128), 256, GEMM_SMEM_BYTES>>>(
        p_an, p_wtq, b_qkv, p_qf16, p_vf16, p_kraw,
        p_x16, p_wtg, b_gate, gate);

    // 2. per-chunk: gate+elu+1 on k, K^T V via MMA, kf16 out
    chunk_kv_kernel<<<dim3(NC, BH), 256>>>(p_kraw, gate, p_vf16, p_kf16, p_kv, p_ksum);

    // 3. exclusive prefix over chunks (one thread per chain)
    scan_kernel<<<(BH * DH * DH + BH * DH) / 256, 256>>>(p_kv, p_ksum, p_sprev, p_ksp);

    // 4. per-chunk attention via MMA
    attn_kernel<<<dim3(NC, BH), 256, ATTN_SMEM_BYTES>>>(
        p_qf16, p_kf16, p_vf16, p_sprev, p_ksp, p_at16);

    // 5. out = attn @ W_proj + b_proj
    gemm_proj<<<dim3(D2 / 128, BL / 128), 256, GEMM_SMEM_BYTES>>>(
        p_at16, p_wtp, b_proj, out);
}

// round 14
// speedup vs baseline: 1.0450x; 1.0025x over previous
#include <cuda_runtime.h>
#include <cuda_fp16.h>
#include <math.h>
#include <stdint.h>

// Problem constants
#define B2   2
#define L2   1024
#define D2   768
#define H2   12
#define DH   64
#define BH   (B2*H2)        // 24
#define BL   (B2*L2)        // 2048
#define N3D  (3*D2)         // 2304
#define CHK  128            // chunk length
#define NC   (L2/CHK)       // 8
#define GK   768            // shared K dim of all GEMMs
#define OUT_ELEMS (BL*D2)   // 1572864

// ---------------- scratch (device globals; no allocation allowed) ----------
__device__ float g_kv[BH*NC*DH*DH];
__device__ float g_ksum[BH*NC*DH];
__device__ float g_sprev[BH*NC*DH*DH];
__device__ float g_ksp[BH*NC*DH];
// fp16 operands (16B-aligned for cp.async / vector loads)
__device__ __align__(256) __half g_kraw16[BL*D2];   // k section fp16 (pre-gate)
__device__ __align__(256) __half g_an[BL*GK];       // LN(x) fp16
__device__ __align__(256) __half g_x16[BL*GK];      // raw x fp16
__device__ __align__(256) __half g_at16[BL*D2];     // attn out fp16
__device__ __align__(256) __half g_qf16[BH*L2*DH];
__device__ __align__(256) __half g_kf16[BH*L2*DH];
__device__ __align__(256) __half g_vf16[BH*L2*DH];
__device__ __align__(256) __half g_wtq[N3D*GK];     // W_qkv^T fp16
__device__ __align__(256) __half g_wtg[D2*GK];      // W_gate^T fp16
__device__ __align__(256) __half g_wtp[D2*GK];      // W_proj^T fp16

// =================== helpers ===============================================
__device__ __forceinline__ uint32_t smem_u32(const void* p) {
    uint32_t a;
    asm("{ .reg .u64 t; cvta.to.shared.u64 t, %1; cvt.u32.u64 %0, t; }"
        : "=r"(a) : "l"(p));
    return a;
}
__device__ __forceinline__ uint32_t sw128(uint32_t off) {
    return off ^ ((off >> 3) & 0x70);
}

#define LDSM4(r0, r1, r2, r3, addr) \
    asm volatile("ldmatrix.sync.aligned.m8n8.x4.shared.b16 {%0,%1,%2,%3}, [%4];" \
        : "=r"(r0), "=r"(r1), "=r"(r2), "=r"(r3) : "r"(addr))

#define MMA_F16(d, a, b) \
    asm volatile("mma.sync.aligned.m16n8k16.row.col.f32.f16.f16.f32 " \
        "{%0,%1,%2,%3},{%4,%5,%6,%7},{%8,%9},{%0,%1,%2,%3};" \
        : "+f"((d)[0]), "+f"((d)[1]), "+f"((d)[2]), "+f"((d)[3]) \
        : "r"((a)[0]), "r"((a)[1]), "r"((a)[2]), "r"((a)[3]), \
          "r"((b)[0]), "r"((b)[1]))

#define CP_ASYNC16(dst, src) \
    asm volatile("cp.async.cg.shared.global [%0], [%1], 16;" \
        :: "r"((uint32_t)(dst)), "l"(src))
#define CP_COMMIT() asm volatile("cp.async.commit_group;" ::: "memory")
#define CP_WAIT(n)  asm volatile("cp.async.wait_group %0;" :: "n"(n) : "memory")

// ------- fused: weight transposes + LayerNorm ------------------------------
// grid.x: [0, 2880) transpose tiles; [2880, 4928) ln rows. 256 threads.
#define NTRB ((N3D + D2 + D2) / 32 * (GK / 32))   // 120*24 = 2880

__global__ void lt_kernel(const float* __restrict__ Wq,
                          const float* __restrict__ Wg,
                          const float* __restrict__ Wp,
                          __half* __restrict__ wtq,
                          __half* __restrict__ wtg,
                          __half* __restrict__ wtp,
                          const float* __restrict__ x,
                          const float* __restrict__ lg,
                          const float* __restrict__ lb,
                          __half* __restrict__ an, __half* __restrict__ x16) {
    __shared__ float t[32][33];
    __shared__ float ss[6], sqs[6];
    int bid = blockIdx.x;
    int tid = threadIdx.x;
    if (bid < NTRB) {
        // ---- transpose tile ----
        int bx = bid % 120;
        int k0 = (bid / 120) * 32;
        const float* W; __half* Wt; int N;
        if (bx < N3D / 32)                { W = Wq; Wt = wtq; N = N3D; }
        else if (bx < N3D / 32 + D2 / 32) { W = Wg; Wt = wtg; N = D2; bx -= N3D / 32; }
        else                              { W = Wp; Wt = wtp; N = D2; bx -= N3D / 32 + D2 / 32; }
        int n0 = bx * 32;
        int tx = tid & 31, ty = tid >> 5;   // 32 x 8
        #pragma unroll
        for (int r = ty; r < 32; r += 8)
            t[r][tx] = W[(size_t)(k0 + r) * N + n0 + tx];
        __syncthreads();
        #pragma unroll
        for (int r = ty; r < 32; r += 8)
            Wt[(size_t)(n0 + r) * GK + k0 + tx] = __float2half_rn(t[tx][r]);
    } else {
        // ---- layernorm row ----
        int row = bid - NTRB;
        float4 v = make_float4(0.f, 0.f, 0.f, 0.f);
        if (tid < 192) v = ((const float4*)(x + (size_t)row * D2))[tid];
        float s  = v.x + v.y + v.z + v.w;
        float sq = v.x*v.x + v.y*v.y + v.z*v.z + v.w*v.w;
        #pragma unroll
        for (int o = 16; o; o >>= 1) {
            s  += __shfl_xor_sync(0xffffffffu, s,  o);
            sq += __shfl_xor_sync(0xffffffffu, sq, o);
        }
        if (tid < 192 && (tid & 31) == 0) { ss[tid >> 5] = s; sqs[tid >> 5] = sq; }
        __syncthreads();
        float ts = 0.f, tq = 0.f;
        #pragma unroll
        for (int w = 0; w < 6; w++) { ts += ss[w]; tq += sqs[w]; }
        float mean = ts * (1.f / D2);
        float var  = tq * (1.f / D2) - mean * mean;
        float inv  = rsqrtf(var + 1e-5f);
        if (tid < 192) {
            int cc = tid * 4;
            float4 gg = ((const float4*)lg)[tid];
            float4 bb = ((const float4*)lb)[tid];
            float n0 = (v.x - mean) * inv * gg.x + bb.x;
            float n1 = (v.y - mean) * inv * gg.y + bb.y;
            float n2 = (v.z - mean) * inv * gg.z + bb.z;
            float n3 = (v.w - mean) * inv * gg.w + bb.w;
            __half2 a01 = __floats2half2_rn(n0, n1);
            __half2 a23 = __floats2half2_rn(n2, n3);
            *(uint2*)(an + (size_t)row * D2 + cc) =
                make_uint2(*(uint32_t*)&a01, *(uint32_t*)&a23);
            __half2 x01 = __floats2half2_rn(v.x, v.y);
            __half2 x23 = __floats2half2_rn(v.z, v.w);
            *(uint2*)(x16 + (size_t)row * D2 + cc) =
                make_uint2(*(uint32_t*)&x01, *(uint32_t*)&x23);
        }
    }
}

// ---------------- fp16 mma.sync GEMM, 2-stage cp.async ---------------------
// EPI: 0 = plain fp32 C, 1 = sigmoid fp32 C, 2 = fused qkv epilogue
#define BKC 64
#define STG_A 0
#define STG_B 16384
#define STAGE_B 32768
#define NSTG 2
#define GEMM_SMEM_BYTES (NSTG * STAGE_B)   // 65536
#define NCHUNK (GK / BKC)   // 12

template <int EPI>
__device__ __forceinline__ void gemm_core(char* smem,
    const __half* __restrict__ Ap, const __half* __restrict__ Bp,
    const float* __restrict__ bias, float* __restrict__ C,
    int Nld, int cb0, int rb0,
    __half* __restrict__ qf, __half* __restrict__ vf,
    __half* __restrict__ kraw16)
{
    uint32_t sb = smem_u32(smem);
    int tid  = threadIdx.x;
    int wid  = tid >> 5, lane = tid & 31;
    int wm   = wid >> 2, wn = wid & 3;        // warp grid 2x4
    int m0   = wm * 64;
    int n0   = wn * 32;
    int lr   = lane & 7, g = lane >> 3;
    int arow = ((g & 1) << 3) + lr;
    int acolb = (g >> 1) << 4;
    int brow = ((g >> 1) << 3) + lr;
    int bcolb = (g & 1) << 4;

    int srow[4], sseg[4]; uint32_t soff[4];
    #pragma unroll
    for (int i = 0; i < 4; i++) {
        int idx = tid + 256 * i;
        srow[i] = idx >> 3;
        sseg[i] = idx & 7;
        soff[i] = sw128((uint32_t)(srow[i] * 128 + sseg[i] * 16));
    }

    float acc[4][4][4];
    #pragma unroll
    for (int mt = 0; mt < 4; mt++)
        #pragma unroll
        for (int nt = 0; nt < 4; nt++)
            #pragma unroll
            for (int q = 0; q < 4; q++) acc[mt][nt][q] = 0.f;

    {
        uint32_t db = sb;
        #pragma unroll
        for (int i = 0; i < 4; i++) {
            size_t off = (size_t)srow[i] * GK + sseg[i] * 8;
            CP_ASYNC16(db + STG_A + soff[i], Ap + off);
            CP_ASYNC16(db + STG_B + soff[i], Bp + off);
        }
        CP_COMMIT();
    }

    for (int c = 0; c < NCHUNK; c++) {
        int st = c & 1;
        CP_WAIT(0);
        __syncthreads();
        if (c + 1 < NCHUNK) {
            uint32_t db = sb + (st ^ 1) * STAGE_B;
            int k0 = (c + 1) * BKC;
            #pragma unroll
            for (int i = 0; i < 4; i++) {
                size_t off = (size_t)srow[i] * GK + k0 + sseg[i] * 8;
                CP_ASYNC16(db + STG_A + soff[i], Ap + off);
                CP_ASYNC16(db + STG_B + soff[i], Bp + off);
            }
            CP_COMMIT();
        }

        uint32_t sA = sb + st * STAGE_B;
        uint32_t sB = sA + STG_B;
        #pragma unroll
        for (int kt = 0; kt < 4; kt++) {
            uint32_t bf[4][2];
            #pragma unroll
            for (int t = 0; t < 2; t++) {
                uint32_t boff = sw128((uint32_t)((n0 + t * 16 + brow) * 128 + kt * 32 + bcolb));
                LDSM4(bf[2*t][0], bf[2*t][1], bf[2*t+1][0], bf[2*t+1][1], sB + boff);
            }
            #pragma unroll
            for (int mt = 0; mt < 4; mt++) {
                uint32_t aoff = sw128((uint32_t)((m0 + mt * 16 + arow) * 128 + kt * 32 + acolb));
                uint32_t af[4];
                LDSM4(af[0], af[1], af[2], af[3], sA + aoff);
                #pragma unroll
                for (int nt = 0; nt < 4; nt++)
                    MMA_F16(acc[mt][nt], af, bf[nt]);
            }
        }
        __syncthreads();
    }

    int rbase = rb0 + m0 + (lane >> 2);
    int cbase = cb0 + n0 + ((lane & 3) << 1);
    if (EPI < 2) {
        #pragma unroll
        for (int mt = 0; mt < 4; mt++) {
            #pragma unroll
            for (int nt = 0; nt < 4; nt++) {
                int col = cbase + nt * 8;
                float b0 = bias[col], b1 = bias[col + 1];
                #pragma unroll
                for (int h = 0; h < 2; h++) {
                    int row = rbase + mt * 16 + h * 8;
                    float o0 = acc[mt][nt][2*h + 0] + b0;
                    float o1 = acc[mt][nt][2*h + 1] + b1;
                    if (EPI == 1) {
                        o0 = 1.f / (1.f + expf(-o0));
                        o1 = 1.f / (1.f + expf(-o1));
                    }
                    *(float2*)(C + (size_t)row * Nld + col) = make_float2(o0, o1);
                }
            }
        }
    } else {
        // qkv epilogue: q -> elu+1 fp16 head layout; v -> fp16 head layout;
        //               k -> fp16 kraw16 (gate applied later inside chunk_kv)
        int sec = cb0 / D2;      // 0=q, 1=k, 2=v (tile never straddles sections)
        if (sec == 1) {
            #pragma unroll
            for (int mt = 0; mt < 4; mt++) {
                #pragma unroll
                for (int nt = 0; nt < 4; nt++) {
                    int col = cbase + nt * 8;
                    int cc  = col - D2;
                    float b0 = bias[col], b1 = bias[col + 1];
                    #pragma unroll
                    for (int h = 0; h < 2; h++) {
                        int row = rbase + mt * 16 + h * 8;
                        float o0 = acc[mt][nt][2*h + 0] + b0;
                        float o1 = acc[mt][nt][2*h + 1] + b1;
                        *(__half2*)(kraw16 + (size_t)row * D2 + cc) =
                            __floats2half2_rn(o0, o1);
                    }
                }
            }
        } else {
            __half* dst = (sec == 0) ? qf : vf;
            #pragma unroll
            for (int mt = 0; mt < 4; mt++) {
                #pragma unroll
                for (int nt = 0; nt < 4; nt++) {
                    int col = cbase + nt * 8;
                    int cc  = col - sec * D2;
                    int hh = cc >> 6, d = cc & 63;
                    float b0 = bias[col], b1 = bias[col + 1];
                    #pragma unroll
                    for (int h = 0; h < 2; h++) {
                        int row = rbase + mt * 16 + h * 8;
                        float o0 = acc[mt][nt][2*h + 0] + b0;
                        float o1 = acc[mt][nt][2*h + 1] + b1;
                        if (sec == 0) {
                            o0 = (o0 > 0.f) ? (o0 + 1.f) : expf(o0);
                            o1 = (o1 > 0.f) ? (o1 + 1.f) : expf(o1);
                        }
                        int b = row >> 10, l = row & 1023;
                        size_t o = ((size_t)(b * H2 + hh) * L2 + l) * DH + d;
                        *(__half2*)(dst + o) = __floats2half2_rn(o0, o1);
                    }
                }
            }
        }
    }
}

// fused QKV + gate GEMM: bx<18 -> QKV tile (fused epilogue), bx>=18 -> gate
__global__ void __launch_bounds__(256, 2) gemm_qkv_gate(
    const __half* __restrict__ xn,  const __half* __restrict__ wq,
    const float* __restrict__ bq,
    __half* __restrict__ qf, __half* __restrict__ vf, __half* __restrict__ kraw16,
    const __half* __restrict__ x16, const __half* __restrict__ wg,
    const float* __restrict__ bg,   float* __restrict__ gateC)
{
    extern __shared__ char smem[];
    int bx = blockIdx.x, by = blockIdx.y;
    if (bx < N3D / 128) {
        gemm_core<2>(smem, xn + (size_t)by * 128 * GK,
                     wq + (size_t)bx * 128 * GK, bq, nullptr, 0,
                     bx * 128, by * 128, qf, vf, kraw16);
    } else {
        int b2 = bx - N3D / 128;
        gemm_core<1>(smem, x16 + (size_t)by * 128 * GK,
                     wg + (size_t)b2 * 128 * GK, bg, gateC, D2,
                     b2 * 128, by * 128, nullptr, nullptr, nullptr);
    }
}

__global__ void __launch_bounds__(256, 2) gemm_proj(
    const __half* __restrict__ at16, const __half* __restrict__ wp,
    const float* __restrict__ bp,    float* __restrict__ outC)
{
    extern __shared__ char smem[];
    gemm_core<0>(smem, at16 + (size_t)blockIdx.y * 128 * GK,
                 wp + (size_t)blockIdx.x * 128 * GK, bp, outC, D2,
                 blockIdx.x * 128, blockIdx.y * 128, nullptr, nullptr, nullptr);
}

// --------- per-chunk: fused kprep + K^T V via MMA + ksum + kf16 ------------
__global__ void chunk_kv_kernel(const __half* __restrict__ kraw16,
                                const float* __restrict__ gate,
                                const __half* __restrict__ vf,
                                __half* __restrict__ kf,
                                float* __restrict__ kv,
                                float* __restrict__ ksum) {
    __shared__ __half sm2[2 * 64 * 136];
    __half* Kt = sm2;
    __half* Vt = sm2 + 64 * 136;
    int c = blockIdx.x, bh = blockIdx.y;
    int bb = bh / H2, hh = bh - bb * H2;
    int tid = threadIdx.x;   // 256
    int wid = tid >> 5, lane = tid & 31;
    const __half* vp = vf + (size_t)(bh * L2 + c * CHK) * DH;
    size_t blbase = (size_t)(bb * L2 + c * CHK);
    __half* kfp = kf + (size_t)(bh * L2 + c * CHK) * DH;
    for (int i = tid; i < CHK * DH; i += 256) {
        int t = i >> 6, d = i & 63;
        size_t gi = (blbase + t) * D2 + hh * DH + d;
        float kvl = __half2float(kraw16[gi]) * gate[gi];
        kvl = (kvl > 0.f) ? (kvl + 1.f) : expf(kvl);
        __half kh = __float2half_rn(kvl);
        Kt[d * 136 + t] = kh;
        kfp[t * DH + d] = kh;
        Vt[d * 136 + t] = vp[t * DH + d];
    }
    __syncthreads();

    uint32_t sb = smem_u32(sm2);
    uint32_t vtb = sb + 64 * 136 * 2;
    int lr = lane & 7, g = lane >> 3;
    int arow = ((g & 1) << 3) + lr;
    int acolb = (g >> 1) << 4;
    int brow = ((g >> 1) << 3) + lr;
    int bcolb = (g & 1) << 4;
    int wm = wid >> 2, wn = wid & 3;
    int m0 = wm * 32, n0 = wn * 16;

    float acc[2][2][4];
    #pragma unroll
    for (int mt = 0; mt < 2; mt++)
        #pragma unroll
        for (int nt = 0; nt < 2; nt++)
            #pragma unroll
            for (int q = 0; q < 4; q++) acc[mt][nt][q] = 0.f;

    #pragma unroll
    for (int kt = 0; kt < 8; kt++) {
        uint32_t bf[2][2];
        uint32_t baddr = vtb + (uint32_t)((n0 + brow) * 272 + kt * 32 + bcolb);
        LDSM4(bf[0][0], bf[0][1], bf[1][0], bf[1][1], baddr);
        #pragma unroll
        for (int mt = 0; mt < 2; mt++) {
            uint32_t aaddr = sb + (uint32_t)((m0 + mt * 16 + arow) * 272 + kt * 32 + acolb);
            uint32_t af[4];
            LDSM4(af[0], af[1], af[2], af[3], aaddr);
            #pragma unroll
            for (int nt = 0; nt < 2; nt++)
                MMA_F16(acc[mt][nt], af, bf[nt]);
        }
    }

    float* kvp = kv + (size_t)(bh * NC + c) * DH * DH;
    int r0 = lane >> 2, cpair = (lane & 3) << 1;
    #pragma unroll
    for (int mt = 0; mt < 2; mt++)
        #pragma unroll
        for (int nt = 0; nt < 2; nt++)
            #pragma unroll
            for (int h = 0; h < 2; h++) {
                int i = m0 + mt * 16 + r0 + 8 * h;
                int j = n0 + nt * 8 + cpair;
                *(float2*)(kvp + i * DH + j) =
                    make_float2(acc[mt][nt][2*h], acc[mt][nt][2*h + 1]);
            }
    if (tid < 64) {
        float s = 0.f;
        const __half2* kr = (const __half2*)(Kt + tid * 136);
        #pragma unroll
        for (int t = 0; t < 64; t++) {
            float2 f = __half22float2(kr[t]);
            s += f.x + f.y;
        }
        ksum[(bh * NC + c) * DH + tid] = s;
    }
}

// ------ exclusive prefix over chunks: one thread per float2 chain ----------
// threads: 24*2048 matrix float2-chains + 24*32 ksum float2-chains = 49920
__global__ void scan_kernel(const float* __restrict__ kv,
                            const float* __restrict__ ksum,
                            float* __restrict__ sprev,
                            float* __restrict__ ksp) {
    int i = blockIdx.x * 256 + threadIdx.x;
    if (i < BH * DH * DH / 2) {
        int bh = i >> 11;
        int e2 = i & 2047;
        float2 acc = make_float2(0.f, 0.f);
        #pragma unroll
        for (int c = 0; c < NC; c++) {
            size_t o = (size_t)(bh * NC + c) * (DH * DH / 2) + e2;
            ((float2*)sprev)[o] = acc;
            float2 v = ((const float2*)kv)[o];
            acc.x += v.x; acc.y += v.y;
        }
    } else {
        int j = i - BH * DH * DH / 2;    // 0..767
        int bh = j >> 5;
        int e2 = j & 31;
        float2 acc = make_float2(0.f, 0.f);
        #pragma unroll
        for (int c = 0; c < NC; c++) {
            size_t o = (size_t)(bh * NC + c) * (DH / 2) + e2;
            ((float2*)ksp)[o] = acc;
            float2 v = ((const float2*)ksum)[o];
            acc.x += v.x; acc.y += v.y;
        }
    }
}

// ---------------- per-chunk attention via MMA ------------------------------
// smem (halves): Q 128x72 @0 | K 128x72 @9216 | Vt 64x136 @18432 |
//                St 64x72 @27136 | Af 128x136 @31744 | floats @98304 (den128,ks64)
#define AQ   0
#define AK   9216
#define AVT  18432
#define AST  27136
#define AAF  31744
#define AFLB 98304
#define ATTN_SMEM_BYTES (AFLB + 768)

__global__ void __launch_bounds__(256) attn_kernel(
        const __half* __restrict__ qf,
        const __half* __restrict__ kf,
        const __half* __restrict__ vf,
        const float* __restrict__ sprev,
        const float* __restrict__ ksp,
        __half* __restrict__ ao16) {
    extern __shared__ __half smh[];
    float* flt = (float*)((char*)smh + AFLB);
    uint32_t sb = smem_u32(smh);
    int c = blockIdx.x, bh = blockIdx.y;
    int tid = threadIdx.x;   // 256
    int wid = tid >> 5, lane = tid & 31;
    const __half* qp = qf + (size_t)(bh * L2 + c * CHK) * DH;
    const __half* kp = kf + (size_t)(bh * L2 + c * CHK) * DH;
    const __half* vp = vf + (size_t)(bh * L2 + c * CHK) * DH;
    const float* sp  = sprev + (size_t)(bh * NC + c) * DH * DH;

    for (int i = tid; i < 1024; i += 256) {
        int row = i >> 3, seg = i & 7;
        *(uint4*)(smh + AQ + row * 72 + seg * 8) = *(const uint4*)(qp + row * DH + seg * 8);
        *(uint4*)(smh + AK + row * 72 + seg * 8) = *(const uint4*)(kp + row * DH + seg * 8);
    }
    for (int i = tid; i < CHK * DH; i += 256) {
        int t = i >> 6, j = i & 63;
        smh[AVT + j * 136 + t] = vp[t * DH + j];
    }
    for (int i = tid; i < DH * DH; i += 256) {
        int d = i >> 6, e = i & 63;
        smh[AST + e * 72 + d] = __float2half_rn(sp[d * DH + e]);
    }
    if (tid < 64) flt[128 + tid] = ksp[(bh * NC + c) * DH + tid];
    __syncthreads();

    int lr = lane & 7, g = lane >> 3;
    int arow = ((g & 1) << 3) + lr;
    int acolb = (g >> 1) << 4;
    int brow = ((g >> 1) << 3) + lr;
    int bcolb = (g & 1) << 4;
    int r0 = lane >> 2, cpair = (lane & 3) << 1;

    // ---- A = QK^T -> causal mask -> fp16 Af ----
    {
        int wm = wid >> 2, wn = wid & 3;
        int m0 = wm * 64, n0 = wn * 32;
        float qa[4][4][4];
        #pragma unroll
        for (int mt = 0; mt < 4; mt++)
            #pragma unroll
            for (int nt = 0; nt < 4; nt++)
                #pragma unroll
                for (int q = 0; q < 4; q++) qa[mt][nt][q] = 0.f;
        #pragma unroll
        for (int kt = 0; kt < 4; kt++) {
            uint32_t bf[4][2];
            #pragma unroll
            for (int t = 0; t < 2; t++) {
                uint32_t baddr = sb + AK * 2 + (uint32_t)((n0 + t * 16 + brow) * 144 + kt * 32 + bcolb);
                LDSM4(bf[2*t][0], bf[2*t][1], bf[2*t+1][0], bf[2*t+1][1], baddr);
            }
            #pragma unroll
            for (int mt = 0; mt < 4; mt++) {
                uint32_t aaddr = sb + AQ * 2 + (uint32_t)((m0 + mt * 16 + arow) * 144 + kt * 32 + acolb);
                uint32_t af[4];
                LDSM4(af[0], af[1], af[2], af[3], aaddr);
                #pragma unroll
                for (int nt = 0; nt < 4; nt++)
                    MMA_F16(qa[mt][nt], af, bf[nt]);
            }
        }
        #pragma unroll
        for (int mt = 0; mt < 4; mt++)
            #pragma unroll
            for (int nt = 0; nt < 4; nt++)
                #pragma unroll
                for (int h = 0; h < 2; h++) {
                    int ai = m0 + mt * 16 + r0 + 8 * h;
                    int aj = n0 + nt * 8 + cpair;
                    float v0 = (aj     <= ai) ? qa[mt][nt][2*h]     : 0.f;
                    float v1 = (aj + 1 <= ai) ? qa[mt][nt][2*h + 1] : 0.f;
                    *(__half2*)(smh + AAF + ai * 136 + aj) = __floats2half2_rn(v0, v1);
                }
    }
    __syncthreads();

    // ---- denominators ----
    if (tid < 128) {
        float s = 0.f;
        const __half2* ar = (const __half2*)(smh + AAF + tid * 136);
        #pragma unroll
        for (int jj = 0; jj < 64; jj++) {
            float2 f = __half22float2(ar[jj]);
            s += f.x + f.y;
        }
        const __half* qr = smh + AQ + tid * 72;
        float qk = 0.f;
        #pragma unroll
        for (int d = 0; d < 64; d++)
            qk += __half2float(qr[d]) * flt[128 + d];
        flt[tid] = s + qk + 1e-6f;
    }
    __syncthreads();

    // ---- O = Af@V + Q@S_prev; divide; write fp16 ----
    {
        int wm2 = wid >> 1, wn2 = wid & 1;
        int m0 = wm2 * 32, n0 = wn2 * 32;
        float oa[2][4][4];
        #pragma unroll
        for (int mt = 0; mt < 2; mt++)
            #pragma unroll
            for (int nt = 0; nt < 4; nt++)
                #pragma unroll
                for (int q = 0; q < 4; q++) oa[mt][nt][q] = 0.f;
        #pragma unroll
        for (int kt = 0; kt < 8; kt++) {
            uint32_t bf[4][2];
            #pragma unroll
            for (int t = 0; t < 2; t++) {
                uint32_t baddr = sb + AVT * 2 + (uint32_t)((n0 + t * 16 + brow) * 272 + kt * 32 + bcolb);
                LDSM4(bf[2*t][0], bf[2*t][1], bf[2*t+1][0], bf[2*t+1][1], baddr);
            }
            #pragma unroll
            for (int mt = 0; mt < 2; mt++) {
                uint32_t aaddr = sb + AAF * 2 + (uint32_t)((m0 + mt * 16 + arow) * 272 + kt * 32 + acolb);
                uint32_t af[4];
                LDSM4(af[0], af[1], af[2], af[3], aaddr);
                #pragma unroll
                for (int nt = 0; nt < 4; nt++)
                    MMA_F16(oa[mt][nt], af, bf[nt]);
            }
        }
        #pragma unroll
        for (int kt = 0; kt < 4; kt++) {
            uint32_t bf[4][2];
            #pragma unroll
            for (int t = 0; t < 2; t++) {
                uint32_t baddr = sb + AST * 2 + (uint32_t)((n0 + t * 16 + brow) * 144 + kt * 32 + bcolb);
                LDSM4(bf[2*t][0], bf[2*t][1], bf[2*t+1][0], bf[2*t+1][1], baddr);
            }
            #pragma unroll
            for (int mt = 0; mt < 2; mt++) {
                uint32_t aaddr = sb + AQ * 2 + (uint32_t)((m0 + mt * 16 + arow) * 144 + kt * 32 + acolb);
                uint32_t af[4];
                LDSM4(af[0], af[1], af[2], af[3], aaddr);
                #pragma unroll
                for (int nt = 0; nt < 4; nt++)
                    MMA_F16(oa[mt][nt], af, bf[nt]);
            }
        }
        int b = bh / H2, hh = bh - b * H2;
        #pragma unroll
        for (int mt = 0; mt < 2; mt++)
            #pragma unroll
            for (int nt = 0; nt < 4; nt++)
                #pragma unroll
                for (int h = 0; h < 2; h++) {
                    int oi = m0 + mt * 16 + r0 + 8 * h;
                    int oj = n0 + nt * 8 + cpair;
                    float dv = flt[oi];
                    float w0 = oa[mt][nt][2*h]     / dv;
                    float w1 = oa[mt][nt][2*h + 1] / dv;
                    int l = c * CHK + oi;
                    *(__half2*)(ao16 + (size_t)(b * L2 + l) * D2 + hh * DH + oj) =
                        __floats2half2_rn(w0, w1);
                }
    }
}

// ---------------- launch ---------------------------------------------------
extern "C" void kernel_launch(void* const* d_in, const int* in_sizes, int n_in,
                              void* d_out, int out_size) {
    const float* x      = (const float*)d_in[0];
    const float* W_qkv  = (const float*)d_in[1];
    const float* b_qkv  = (const float*)d_in[2];
    const float* W_gate = (const float*)d_in[3];
    const float* b_gate = (const float*)d_in[4];
    const float* W_proj = (const float*)d_in[5];
    const float* b_proj = (const float*)d_in[6];
    const float* ln_g   = (const float*)d_in[7];
    const float* ln_b   = (const float*)d_in[8];
    float* out  = (float*)d_out;           // proj output
    float* gate = out + OUT_ELEMS;         // gate output (2nd return value)

    float *p_kv, *p_ksum, *p_sprev, *p_ksp;
    __half *p_kraw16, *p_an, *p_x16, *p_at16, *p_wtq, *p_wtg, *p_wtp;
    __half *p_qf16, *p_kf16, *p_vf16;
    cudaGetSymbolAddress((void**)&p_kraw16, g_kraw16);
    cudaGetSymbolAddress((void**)&p_kv,    g_kv);
    cudaGetSymbolAddress((void**)&p_ksum,  g_ksum);
    cudaGetSymbolAddress((void**)&p_sprev, g_sprev);
    cudaGetSymbolAddress((void**)&p_ksp,   g_ksp);
    cudaGetSymbolAddress((void**)&p_an,    g_an);
    cudaGetSymbolAddress((void**)&p_x16,   g_x16);
    cudaGetSymbolAddress((void**)&p_at16,  g_at16);
    cudaGetSymbolAddress((void**)&p_wtq,   g_wtq);
    cudaGetSymbolAddress((void**)&p_wtg,   g_wtg);
    cudaGetSymbolAddress((void**)&p_wtp,   g_wtp);
    cudaGetSymbolAddress((void**)&p_qf16,  g_qf16);
    cudaGetSymbolAddress((void**)&p_kf16,  g_kf16);
    cudaGetSymbolAddress((void**)&p_vf16,  g_vf16);

    cudaFuncSetAttribute(gemm_qkv_gate, cudaFuncAttributeMaxDynamicSharedMemorySize,
                         GEMM_SMEM_BYTES);
    cudaFuncSetAttribute(gemm_proj, cudaFuncAttributeMaxDynamicSharedMemorySize,
                         GEMM_SMEM_BYTES);
    cudaFuncSetAttribute(attn_kernel, cudaFuncAttributeMaxDynamicSharedMemorySize,
                         ATTN_SMEM_BYTES);

    // 0. fused: weight transposes + LayerNorm (one launch)
    lt_kernel<<<NTRB + BL, 256>>>(W_qkv, W_gate, W_proj, p_wtq, p_wtg, p_wtp,
                                  x, ln_g, ln_b, p_an, p_x16);

    // 1. fused QKV + gate GEMM (q,v finished in epilogue; k -> fp16 kraw16)
    gemm_qkv_gate<<<dim3(N3D / 128 + D2 / 128, BL / 128), 256, GEMM_SMEM_BYTES>>>(
        p_an, p_wtq, b_qkv, p_qf16, p_vf16, p_kraw16,
        p_x16, p_wtg, b_gate, gate);

    // 2. per-chunk: gate+elu+1 on k, K^T V via MMA, kf16 out
    chunk_kv_kernel<<<dim3(NC, BH), 256>>>(p_kraw16, gate, p_vf16, p_kf16, p_kv, p_ksum);

    // 3. exclusive prefix over chunks (one thread per float2 chain)
    scan_kernel<<<(BH * DH * DH / 2 + BH * DH / 2) / 256, 256>>>(
        p_kv, p_ksum, p_sprev, p_ksp);

    // 4. per-chunk attention via MMA
    attn_kernel<<<dim3(NC, BH), 256, ATTN_SMEM_BYTES>>>(
        p_qf16, p_kf16, p_vf16, p_sprev, p_ksp, p_at16);

    // 5. out = attn @ W_proj + b_proj
    gemm_proj<<<dim3(D2 / 128, BL / 128), 256, GEMM_SMEM_BYTES>>>(
        p_at16, p_wtp, b_proj, out);
}

// round 15
// speedup vs baseline: 1.0989x; 1.0515x over previous
#include <cuda_runtime.h>
#include <cuda_fp16.h>
#include <math.h>
#include <stdint.h>

// Problem constants
#define B2   2
#define L2   1024
#define D2   768
#define H2   12
#define DH   64
#define BH   (B2*H2)        // 24
#define BL   (B2*L2)        // 2048
#define N3D  (3*D2)         // 2304
#define CHK  128            // chunk length
#define NC   (L2/CHK)       // 8
#define GK   768            // shared K dim of all GEMMs
#define OUT_ELEMS (BL*D2)   // 1572864

// ---------------- scratch (device globals; no allocation allowed) ----------
__device__ float g_kv[BH*NC*DH*DH];
__device__ float g_ksum[BH*NC*DH];
// fp16 operands (16B-aligned for cp.async / vector loads)
__device__ __align__(256) __half g_kraw16[BL*D2];   // k section fp16 (pre-gate)
__device__ __align__(256) __half g_an[BL*GK];       // LN(x) fp16
__device__ __align__(256) __half g_x16[BL*GK];      // raw x fp16
__device__ __align__(256) __half g_at16[BL*D2];     // attn out fp16
__device__ __align__(256) __half g_qf16[BH*L2*DH];
__device__ __align__(256) __half g_kf16[BH*L2*DH];
__device__ __align__(256) __half g_vf16[BH*L2*DH];
__device__ __align__(256) __half g_wtq[N3D*GK];     // W_qkv^T fp16
__device__ __align__(256) __half g_wtg[D2*GK];      // W_gate^T fp16
__device__ __align__(256) __half g_wtp[D2*GK];      // W_proj^T fp16

// =================== helpers ===============================================
__device__ __forceinline__ uint32_t smem_u32(const void* p) {
    uint32_t a;
    asm("{ .reg .u64 t; cvta.to.shared.u64 t, %1; cvt.u32.u64 %0, t; }"
        : "=r"(a) : "l"(p));
    return a;
}
__device__ __forceinline__ uint32_t sw128(uint32_t off) {
    return off ^ ((off >> 3) & 0x70);
}

#define LDSM4(r0, r1, r2, r3, addr) \
    asm volatile("ldmatrix.sync.aligned.m8n8.x4.shared.b16 {%0,%1,%2,%3}, [%4];" \
        : "=r"(r0), "=r"(r1), "=r"(r2), "=r"(r3) : "r"(addr))

#define MMA_F16(d, a, b) \
    asm volatile("mma.sync.aligned.m16n8k16.row.col.f32.f16.f16.f32 " \
        "{%0,%1,%2,%3},{%4,%5,%6,%7},{%8,%9},{%0,%1,%2,%3};" \
        : "+f"((d)[0]), "+f"((d)[1]), "+f"((d)[2]), "+f"((d)[3]) \
        : "r"((a)[0]), "r"((a)[1]), "r"((a)[2]), "r"((a)[3]), \
          "r"((b)[0]), "r"((b)[1]))

#define CP_ASYNC16(dst, src) \
    asm volatile("cp.async.cg.shared.global [%0], [%1], 16;" \
        :: "r"((uint32_t)(dst)), "l"(src))
#define CP_COMMIT() asm volatile("cp.async.commit_group;" ::: "memory")
#define CP_WAIT(n)  asm volatile("cp.async.wait_group %0;" :: "n"(n) : "memory")

// ------- fused: weight transposes + LayerNorm ------------------------------
// grid.x: [0, 2880) transpose tiles; [2880, 4928) ln rows. 256 threads.
#define NTRB ((N3D + D2 + D2) / 32 * (GK / 32))   // 120*24 = 2880

__global__ void lt_kernel(const float* __restrict__ Wq,
                          const float* __restrict__ Wg,
                          const float* __restrict__ Wp,
                          __half* __restrict__ wtq,
                          __half* __restrict__ wtg,
                          __half* __restrict__ wtp,
                          const float* __restrict__ x,
                          const float* __restrict__ lg,
                          const float* __restrict__ lb,
                          __half* __restrict__ an, __half* __restrict__ x16) {
    __shared__ float t[32][33];
    __shared__ float ss[6], sqs[6];
    int bid = blockIdx.x;
    int tid = threadIdx.x;
    if (bid < NTRB) {
        // ---- transpose tile ----
        int bx = bid % 120;
        int k0 = (bid / 120) * 32;
        const float* W; __half* Wt; int N;
        if (bx < N3D / 32)                { W = Wq; Wt = wtq; N = N3D; }
        else if (bx < N3D / 32 + D2 / 32) { W = Wg; Wt = wtg; N = D2; bx -= N3D / 32; }
        else                              { W = Wp; Wt = wtp; N = D2; bx -= N3D / 32 + D2 / 32; }
        int n0 = bx * 32;
        int tx = tid & 31, ty = tid >> 5;   // 32 x 8
        #pragma unroll
        for (int r = ty; r < 32; r += 8)
            t[r][tx] = W[(size_t)(k0 + r) * N + n0 + tx];
        __syncthreads();
        #pragma unroll
        for (int r = ty; r < 32; r += 8)
            Wt[(size_t)(n0 + r) * GK + k0 + tx] = __float2half_rn(t[tx][r]);
    } else {
        // ---- layernorm row ----
        int row = bid - NTRB;
        float4 v = make_float4(0.f, 0.f, 0.f, 0.f);
        if (tid < 192) v = ((const float4*)(x + (size_t)row * D2))[tid];
        float s  = v.x + v.y + v.z + v.w;
        float sq = v.x*v.x + v.y*v.y + v.z*v.z + v.w*v.w;
        #pragma unroll
        for (int o = 16; o; o >>= 1) {
            s  += __shfl_xor_sync(0xffffffffu, s,  o);
            sq += __shfl_xor_sync(0xffffffffu, sq, o);
        }
        if (tid < 192 && (tid & 31) == 0) { ss[tid >> 5] = s; sqs[tid >> 5] = sq; }
        __syncthreads();
        float ts = 0.f, tq = 0.f;
        #pragma unroll
        for (int w = 0; w < 6; w++) { ts += ss[w]; tq += sqs[w]; }
        float mean = ts * (1.f / D2);
        float var  = tq * (1.f / D2) - mean * mean;
        float inv  = rsqrtf(var + 1e-5f);
        if (tid < 192) {
            int cc = tid * 4;
            float4 gg = ((const float4*)lg)[tid];
            float4 bb = ((const float4*)lb)[tid];
            float n0 = (v.x - mean) * inv * gg.x + bb.x;
            float n1 = (v.y - mean) * inv * gg.y + bb.y;
            float n2 = (v.z - mean) * inv * gg.z + bb.z;
            float n3 = (v.w - mean) * inv * gg.w + bb.w;
            __half2 a01 = __floats2half2_rn(n0, n1);
            __half2 a23 = __floats2half2_rn(n2, n3);
            *(uint2*)(an + (size_t)row * D2 + cc) =
                make_uint2(*(uint32_t*)&a01, *(uint32_t*)&a23);
            __half2 x01 = __floats2half2_rn(v.x, v.y);
            __half2 x23 = __floats2half2_rn(v.z, v.w);
            *(uint2*)(x16 + (size_t)row * D2 + cc) =
                make_uint2(*(uint32_t*)&x01, *(uint32_t*)&x23);
        }
    }
}

// ---------------- fp16 mma.sync GEMM, 2-stage cp.async ---------------------
// EPI: 0 = plain fp32 C, 1 = sigmoid fp32 C, 2 = fused qkv epilogue
#define BKC 64
#define STG_A 0
#define STG_B 16384
#define STAGE_B 32768
#define NSTG 2
#define GEMM_SMEM_BYTES (NSTG * STAGE_B)   // 65536
#define NCHUNK (GK / BKC)   // 12

template <int EPI>
__device__ __forceinline__ void gemm_core(char* smem,
    const __half* __restrict__ Ap, const __half* __restrict__ Bp,
    const float* __restrict__ bias, float* __restrict__ C,
    int Nld, int cb0, int rb0,
    __half* __restrict__ qf, __half* __restrict__ vf,
    __half* __restrict__ kraw16)
{
    uint32_t sb = smem_u32(smem);
    int tid  = threadIdx.x;
    int wid  = tid >> 5, lane = tid & 31;
    int wm   = wid >> 2, wn = wid & 3;        // warp grid 2x4
    int m0   = wm * 64;
    int n0   = wn * 32;
    int lr   = lane & 7, g = lane >> 3;
    int arow = ((g & 1) << 3) + lr;
    int acolb = (g >> 1) << 4;
    int brow = ((g >> 1) << 3) + lr;
    int bcolb = (g & 1) << 4;

    int srow[4], sseg[4]; uint32_t soff[4];
    #pragma unroll
    for (int i = 0; i < 4; i++) {
        int idx = tid + 256 * i;
        srow[i] = idx >> 3;
        sseg[i] = idx & 7;
        soff[i] = sw128((uint32_t)(srow[i] * 128 + sseg[i] * 16));
    }

    float acc[4][4][4];
    #pragma unroll
    for (int mt = 0; mt < 4; mt++)
        #pragma unroll
        for (int nt = 0; nt < 4; nt++)
            #pragma unroll
            for (int q = 0; q < 4; q++) acc[mt][nt][q] = 0.f;

    {
        uint32_t db = sb;
        #pragma unroll
        for (int i = 0; i < 4; i++) {
            size_t off = (size_t)srow[i] * GK + sseg[i] * 8;
            CP_ASYNC16(db + STG_A + soff[i], Ap + off);
            CP_ASYNC16(db + STG_B + soff[i], Bp + off);
        }
        CP_COMMIT();
    }

    for (int c = 0; c < NCHUNK; c++) {
        int st = c & 1;
        CP_WAIT(0);
        __syncthreads();
        if (c + 1 < NCHUNK) {
            uint32_t db = sb + (st ^ 1) * STAGE_B;
            int k0 = (c + 1) * BKC;
            #pragma unroll
            for (int i = 0; i < 4; i++) {
                size_t off = (size_t)srow[i] * GK + k0 + sseg[i] * 8;
                CP_ASYNC16(db + STG_A + soff[i], Ap + off);
                CP_ASYNC16(db + STG_B + soff[i], Bp + off);
            }
            CP_COMMIT();
        }

        uint32_t sA = sb + st * STAGE_B;
        uint32_t sB = sA + STG_B;
        #pragma unroll
        for (int kt = 0; kt < 4; kt++) {
            uint32_t bf[4][2];
            #pragma unroll
            for (int t = 0; t < 2; t++) {
                uint32_t boff = sw128((uint32_t)((n0 + t * 16 + brow) * 128 + kt * 32 + bcolb));
                LDSM4(bf[2*t][0], bf[2*t][1], bf[2*t+1][0], bf[2*t+1][1], sB + boff);
            }
            #pragma unroll
            for (int mt = 0; mt < 4; mt++) {
                uint32_t aoff = sw128((uint32_t)((m0 + mt * 16 + arow) * 128 + kt * 32 + acolb));
                uint32_t af[4];
                LDSM4(af[0], af[1], af[2], af[3], sA + aoff);
                #pragma unroll
                for (int nt = 0; nt < 4; nt++)
                    MMA_F16(acc[mt][nt], af, bf[nt]);
            }
        }
        __syncthreads();
    }

    int rbase = rb0 + m0 + (lane >> 2);
    int cbase = cb0 + n0 + ((lane & 3) << 1);
    if (EPI < 2) {
        #pragma unroll
        for (int mt = 0; mt < 4; mt++) {
            #pragma unroll
            for (int nt = 0; nt < 4; nt++) {
                int col = cbase + nt * 8;
                float b0 = bias[col], b1 = bias[col + 1];
                #pragma unroll
                for (int h = 0; h < 2; h++) {
                    int row = rbase + mt * 16 + h * 8;
                    float o0 = acc[mt][nt][2*h + 0] + b0;
                    float o1 = acc[mt][nt][2*h + 1] + b1;
                    if (EPI == 1) {
                        o0 = 1.f / (1.f + expf(-o0));
                        o1 = 1.f / (1.f + expf(-o1));
                    }
                    *(float2*)(C + (size_t)row * Nld + col) = make_float2(o0, o1);
                }
            }
        }
    } else {
        // qkv epilogue: q -> elu+1 fp16 head layout; v -> fp16 head layout;
        //               k -> fp16 kraw16 (gate applied later inside chunk_kv)
        int sec = cb0 / D2;      // 0=q, 1=k, 2=v (tile never straddles sections)
        if (sec == 1) {
            #pragma unroll
            for (int mt = 0; mt < 4; mt++) {
                #pragma unroll
                for (int nt = 0; nt < 4; nt++) {
                    int col = cbase + nt * 8;
                    int cc  = col - D2;
                    float b0 = bias[col], b1 = bias[col + 1];
                    #pragma unroll
                    for (int h = 0; h < 2; h++) {
                        int row = rbase + mt * 16 + h * 8;
                        float o0 = acc[mt][nt][2*h + 0] + b0;
                        float o1 = acc[mt][nt][2*h + 1] + b1;
                        *(__half2*)(kraw16 + (size_t)row * D2 + cc) =
                            __floats2half2_rn(o0, o1);
                    }
                }
            }
        } else {
            __half* dst = (sec == 0) ? qf : vf;
            #pragma unroll
            for (int mt = 0; mt < 4; mt++) {
                #pragma unroll
                for (int nt = 0; nt < 4; nt++) {
                    int col = cbase + nt * 8;
                    int cc  = col - sec * D2;
                    int hh = cc >> 6, d = cc & 63;
                    float b0 = bias[col], b1 = bias[col + 1];
                    #pragma unroll
                    for (int h = 0; h < 2; h++) {
                        int row = rbase + mt * 16 + h * 8;
                        float o0 = acc[mt][nt][2*h + 0] + b0;
                        float o1 = acc[mt][nt][2*h + 1] + b1;
                        if (sec == 0) {
                            o0 = (o0 > 0.f) ? (o0 + 1.f) : expf(o0);
                            o1 = (o1 > 0.f) ? (o1 + 1.f) : expf(o1);
                        }
                        int b = row >> 10, l = row & 1023;
                        size_t o = ((size_t)(b * H2 + hh) * L2 + l) * DH + d;
                        *(__half2*)(dst + o) = __floats2half2_rn(o0, o1);
                    }
                }
            }
        }
    }
}

// fused QKV + gate GEMM: bx<18 -> QKV tile (fused epilogue), bx>=18 -> gate
__global__ void __launch_bounds__(256, 2) gemm_qkv_gate(
    const __half* __restrict__ xn,  const __half* __restrict__ wq,
    const float* __restrict__ bq,
    __half* __restrict__ qf, __half* __restrict__ vf, __half* __restrict__ kraw16,
    const __half* __restrict__ x16, const __half* __restrict__ wg,
    const float* __restrict__ bg,   float* __restrict__ gateC)
{
    extern __shared__ char smem[];
    int bx = blockIdx.x, by = blockIdx.y;
    if (bx < N3D / 128) {
        gemm_core<2>(smem, xn + (size_t)by * 128 * GK,
                     wq + (size_t)bx * 128 * GK, bq, nullptr, 0,
                     bx * 128, by * 128, qf, vf, kraw16);
    } else {
        int b2 = bx - N3D / 128;
        gemm_core<1>(smem, x16 + (size_t)by * 128 * GK,
                     wg + (size_t)b2 * 128 * GK, bg, gateC, D2,
                     b2 * 128, by * 128, nullptr, nullptr, nullptr);
    }
}

__global__ void __launch_bounds__(256, 2) gemm_proj(
    const __half* __restrict__ at16, const __half* __restrict__ wp,
    const float* __restrict__ bp,    float* __restrict__ outC)
{
    extern __shared__ char smem[];
    gemm_core<0>(smem, at16 + (size_t)blockIdx.y * 128 * GK,
                 wp + (size_t)blockIdx.x * 128 * GK, bp, outC, D2,
                 blockIdx.x * 128, blockIdx.y * 128, nullptr, nullptr, nullptr);
}

// --------- per-chunk: fused kprep + K^T V via MMA + ksum + kf16 ------------
__global__ void chunk_kv_kernel(const __half* __restrict__ kraw16,
                                const float* __restrict__ gate,
                                const __half* __restrict__ vf,
                                __half* __restrict__ kf,
                                float* __restrict__ kv,
                                float* __restrict__ ksum) {
    __shared__ __half sm2[2 * 64 * 136];
    __half* Kt = sm2;
    __half* Vt = sm2 + 64 * 136;
    int c = blockIdx.x, bh = blockIdx.y;
    int bb = bh / H2, hh = bh - bb * H2;
    int tid = threadIdx.x;   // 256
    int wid = tid >> 5, lane = tid & 31;
    const __half* vp = vf + (size_t)(bh * L2 + c * CHK) * DH;
    size_t blbase = (size_t)(bb * L2 + c * CHK);
    __half* kfp = kf + (size_t)(bh * L2 + c * CHK) * DH;
    for (int i = tid; i < CHK * DH; i += 256) {
        int t = i >> 6, d = i & 63;
        size_t gi = (blbase + t) * D2 + hh * DH + d;
        float kvl = __half2float(kraw16[gi]) * gate[gi];
        kvl = (kvl > 0.f) ? (kvl + 1.f) : expf(kvl);
        __half kh = __float2half_rn(kvl);
        Kt[d * 136 + t] = kh;
        kfp[t * DH + d] = kh;
        Vt[d * 136 + t] = vp[t * DH + d];
    }
    __syncthreads();

    uint32_t sb = smem_u32(sm2);
    uint32_t vtb = sb + 64 * 136 * 2;
    int lr = lane & 7, g = lane >> 3;
    int arow = ((g & 1) << 3) + lr;
    int acolb = (g >> 1) << 4;
    int brow = ((g >> 1) << 3) + lr;
    int bcolb = (g & 1) << 4;
    int wm = wid >> 2, wn = wid & 3;
    int m0 = wm * 32, n0 = wn * 16;

    float acc[2][2][4];
    #pragma unroll
    for (int mt = 0; mt < 2; mt++)
        #pragma unroll
        for (int nt = 0; nt < 2; nt++)
            #pragma unroll
            for (int q = 0; q < 4; q++) acc[mt][nt][q] = 0.f;

    #pragma unroll
    for (int kt = 0; kt < 8; kt++) {
        uint32_t bf[2][2];
        uint32_t baddr = vtb + (uint32_t)((n0 + brow) * 272 + kt * 32 + bcolb);
        LDSM4(bf[0][0], bf[0][1], bf[1][0], bf[1][1], baddr);
        #pragma unroll
        for (int mt = 0; mt < 2; mt++) {
            uint32_t aaddr = sb + (uint32_t)((m0 + mt * 16 + arow) * 272 + kt * 32 + acolb);
            uint32_t af[4];
            LDSM4(af[0], af[1], af[2], af[3], aaddr);
            #pragma unroll
            for (int nt = 0; nt < 2; nt++)
                MMA_F16(acc[mt][nt], af, bf[nt]);
        }
    }

    float* kvp = kv + (size_t)(bh * NC + c) * DH * DH;
    int r0 = lane >> 2, cpair = (lane & 3) << 1;
    #pragma unroll
    for (int mt = 0; mt < 2; mt++)
        #pragma unroll
        for (int nt = 0; nt < 2; nt++)
            #pragma unroll
            for (int h = 0; h < 2; h++) {
                int i = m0 + mt * 16 + r0 + 8 * h;
                int j = n0 + nt * 8 + cpair;
                *(float2*)(kvp + i * DH + j) =
                    make_float2(acc[mt][nt][2*h], acc[mt][nt][2*h + 1]);
            }
    if (tid < 64) {
        float s = 0.f;
        const __half2* kr = (const __half2*)(Kt + tid * 136);
        #pragma unroll
        for (int t = 0; t < 64; t++) {
            float2 f = __half22float2(kr[t]);
            s += f.x + f.y;
        }
        ksum[(bh * NC + c) * DH + tid] = s;
    }
}

// ---------------- per-chunk attention via MMA (fused chunk-prefix) ---------
// smem (halves): Q 128x72 @0 | K 128x72 @9216 | Vt 64x136 @18432 |
//                St 64x72 @27136 | Af 128x136 @31744 | floats @98304 (den128,ks64)
#define AQ   0
#define AK   9216
#define AVT  18432
#define AST  27136
#define AAF  31744
#define AFLB 98304
#define ATTN_SMEM_BYTES (AFLB + 768)

__global__ void __launch_bounds__(256) attn_kernel(
        const __half* __restrict__ qf,
        const __half* __restrict__ kf,
        const __half* __restrict__ vf,
        const float* __restrict__ kv,
        const float* __restrict__ ksum,
        __half* __restrict__ ao16) {
    extern __shared__ __half smh[];
    float* flt = (float*)((char*)smh + AFLB);
    uint32_t sb = smem_u32(smh);
    int c = blockIdx.x, bh = blockIdx.y;
    int tid = threadIdx.x;   // 256
    int wid = tid >> 5, lane = tid & 31;
    const __half* qp = qf + (size_t)(bh * L2 + c * CHK) * DH;
    const __half* kp = kf + (size_t)(bh * L2 + c * CHK) * DH;
    const __half* vp = vf + (size_t)(bh * L2 + c * CHK) * DH;

    for (int i = tid; i < 1024; i += 256) {
        int row = i >> 3, seg = i & 7;
        *(uint4*)(smh + AQ + row * 72 + seg * 8) = *(const uint4*)(qp + row * DH + seg * 8);
        *(uint4*)(smh + AK + row * 72 + seg * 8) = *(const uint4*)(kp + row * DH + seg * 8);
    }
    for (int i = tid; i < CHK * DH; i += 256) {
        int t = i >> 6, j = i & 63;
        smh[AVT + j * 136 + t] = vp[t * DH + j];
    }
    // fused prefix: S_prev = sum_{cc<c} kv[cc]; stored transposed to St (fp16)
    {
        float sacc[16];
        #pragma unroll
        for (int r = 0; r < 16; r++) sacc[r] = 0.f;
        const float* kvb = kv + (size_t)(bh * NC) * (DH * DH);
        for (int cc = 0; cc < c; cc++) {
            const float* kp2 = kvb + (size_t)cc * (DH * DH);
            #pragma unroll
            for (int r = 0; r < 16; r++)
                sacc[r] += kp2[tid + 256 * r];
        }
        #pragma unroll
        for (int r = 0; r < 16; r++) {
            int idx = tid + 256 * r;
            int d = idx >> 6, e = idx & 63;
            smh[AST + e * 72 + d] = __float2half_rn(sacc[r]);
        }
    }
    if (tid < 64) {
        float a = 0.f;
        const float* ksb = ksum + (size_t)(bh * NC) * DH + tid;
        for (int cc = 0; cc < c; cc++) a += ksb[cc * DH];
        flt[128 + tid] = a;
    }
    __syncthreads();

    int lr = lane & 7, g = lane >> 3;
    int arow = ((g & 1) << 3) + lr;
    int acolb = (g >> 1) << 4;
    int brow = ((g >> 1) << 3) + lr;
    int bcolb = (g & 1) << 4;
    int r0 = lane >> 2, cpair = (lane & 3) << 1;

    // ---- A = QK^T -> causal mask -> fp16 Af ----
    {
        int wm = wid >> 2, wn = wid & 3;
        int m0 = wm * 64, n0 = wn * 32;
        float qa[4][4][4];
        #pragma unroll
        for (int mt = 0; mt < 4; mt++)
            #pragma unroll
            for (int nt = 0; nt < 4; nt++)
                #pragma unroll
                for (int q = 0; q < 4; q++) qa[mt][nt][q] = 0.f;
        #pragma unroll
        for (int kt = 0; kt < 4; kt++) {
            uint32_t bf[4][2];
            #pragma unroll
            for (int t = 0; t < 2; t++) {
                uint32_t baddr = sb + AK * 2 + (uint32_t)((n0 + t * 16 + brow) * 144 + kt * 32 + bcolb);
                LDSM4(bf[2*t][0], bf[2*t][1], bf[2*t+1][0], bf[2*t+1][1], baddr);
            }
            #pragma unroll
            for (int mt = 0; mt < 4; mt++) {
                uint32_t aaddr = sb + AQ * 2 + (uint32_t)((m0 + mt * 16 + arow) * 144 + kt * 32 + acolb);
                uint32_t af[4];
                LDSM4(af[0], af[1], af[2], af[3], aaddr);
                #pragma unroll
                for (int nt = 0; nt < 4; nt++)
                    MMA_F16(qa[mt][nt], af, bf[nt]);
            }
        }
        #pragma unroll
        for (int mt = 0; mt < 4; mt++)
            #pragma unroll
            for (int nt = 0; nt < 4; nt++)
                #pragma unroll
                for (int h = 0; h < 2; h++) {
                    int ai = m0 + mt * 16 + r0 + 8 * h;
                    int aj = n0 + nt * 8 + cpair;
                    float v0 = (aj     <= ai) ? qa[mt][nt][2*h]     : 0.f;
                    float v1 = (aj + 1 <= ai) ? qa[mt][nt][2*h + 1] : 0.f;
                    *(__half2*)(smh + AAF + ai * 136 + aj) = __floats2half2_rn(v0, v1);
                }
    }
    __syncthreads();

    // ---- denominators ----
    if (tid < 128) {
        float s = 0.f;
        const __half2* ar = (const __half2*)(smh + AAF + tid * 136);
        #pragma unroll
        for (int jj = 0; jj < 64; jj++) {
            float2 f = __half22float2(ar[jj]);
            s += f.x + f.y;
        }
        const __half* qr = smh + AQ + tid * 72;
        float qk = 0.f;
        #pragma unroll
        for (int d = 0; d < 64; d++)
            qk += __half2float(qr[d]) * flt[128 + d];
        flt[tid] = s + qk + 1e-6f;
    }
    __syncthreads();

    // ---- O = Af@V + Q@S_prev; divide; write fp16 ----
    {
        int wm2 = wid >> 1, wn2 = wid & 1;
        int m0 = wm2 * 32, n0 = wn2 * 32;
        float oa[2][4][4];
        #pragma unroll
        for (int mt = 0; mt < 2; mt++)
            #pragma unroll
            for (int nt = 0; nt < 4; nt++)
                #pragma unroll
                for (int q = 0; q < 4; q++) oa[mt][nt][q] = 0.f;
        #pragma unroll
        for (int kt = 0; kt < 8; kt++) {
            uint32_t bf[4][2];
            #pragma unroll
            for (int t = 0; t < 2; t++) {
                uint32_t baddr = sb + AVT * 2 + (uint32_t)((n0 + t * 16 + brow) * 272 + kt * 32 + bcolb);
                LDSM4(bf[2*t][0], bf[2*t][1], bf[2*t+1][0], bf[2*t+1][1], baddr);
            }
            #pragma unroll
            for (int mt = 0; mt < 2; mt++) {
                uint32_t aaddr = sb + AAF * 2 + (uint32_t)((m0 + mt * 16 + arow) * 272 + kt * 32 + acolb);
                uint32_t af[4];
                LDSM4(af[0], af[1], af[2], af[3], aaddr);
                #pragma unroll
                for (int nt = 0; nt < 4; nt++)
                    MMA_F16(oa[mt][nt], af, bf[nt]);
            }
        }
        #pragma unroll
        for (int kt = 0; kt < 4; kt++) {
            uint32_t bf[4][2];
            #pragma unroll
            for (int t = 0; t < 2; t++) {
                uint32_t baddr = sb + AST * 2 + (uint32_t)((n0 + t * 16 + brow) * 144 + kt * 32 + bcolb);
                LDSM4(bf[2*t][0], bf[2*t][1], bf[2*t+1][0], bf[2*t+1][1], baddr);
            }
            #pragma unroll
            for (int mt = 0; mt < 2; mt++) {
                uint32_t aaddr = sb + AQ * 2 + (uint32_t)((m0 + mt * 16 + arow) * 144 + kt * 32 + acolb);
                uint32_t af[4];
                LDSM4(af[0], af[1], af[2], af[3], aaddr);
                #pragma unroll
                for (int nt = 0; nt < 4; nt++)
                    MMA_F16(oa[mt][nt], af, bf[nt]);
            }
        }
        int b = bh / H2, hh = bh - b * H2;
        #pragma unroll
        for (int mt = 0; mt < 2; mt++)
            #pragma unroll
            for (int nt = 0; nt < 4; nt++)
                #pragma unroll
                for (int h = 0; h < 2; h++) {
                    int oi = m0 + mt * 16 + r0 + 8 * h;
                    int oj = n0 + nt * 8 + cpair;
                    float dv = flt[oi];
                    float w0 = oa[mt][nt][2*h]     / dv;
                    float w1 = oa[mt][nt][2*h + 1] / dv;
                    int l = c * CHK + oi;
                    *(__half2*)(ao16 + (size_t)(b * L2 + l) * D2 + hh * DH + oj) =
                        __floats2half2_rn(w0, w1);
                }
    }
}

// ---------------- launch ---------------------------------------------------
extern "C" void kernel_launch(void* const* d_in, const int* in_sizes, int n_in,
                              void* d_out, int out_size) {
    const float* x      = (const float*)d_in[0];
    const float* W_qkv  = (const float*)d_in[1];
    const float* b_qkv  = (const float*)d_in[2];
    const float* W_gate = (const float*)d_in[3];
    const float* b_gate = (const float*)d_in[4];
    const float* W_proj = (const float*)d_in[5];
    const float* b_proj = (const float*)d_in[6];
    const float* ln_g   = (const float*)d_in[7];
    const float* ln_b   = (const float*)d_in[8];
    float* out  = (float*)d_out;           // proj output
    float* gate = out + OUT_ELEMS;         // gate output (2nd return value)

    float *p_kv, *p_ksum;
    __half *p_kraw16, *p_an, *p_x16, *p_at16, *p_wtq, *p_wtg, *p_wtp;
    __half *p_qf16, *p_kf16, *p_vf16;
    cudaGetSymbolAddress((void**)&p_kraw16, g_kraw16);
    cudaGetSymbolAddress((void**)&p_kv,    g_kv);
    cudaGetSymbolAddress((void**)&p_ksum,  g_ksum);
    cudaGetSymbolAddress((void**)&p_an,    g_an);
    cudaGetSymbolAddress((void**)&p_x16,   g_x16);
    cudaGetSymbolAddress((void**)&p_at16,  g_at16);
    cudaGetSymbolAddress((void**)&p_wtq,   g_wtq);
    cudaGetSymbolAddress((void**)&p_wtg,   g_wtg);
    cudaGetSymbolAddress((void**)&p_wtp,   g_wtp);
    cudaGetSymbolAddress((void**)&p_qf16,  g_qf16);
    cudaGetSymbolAddress((void**)&p_kf16,  g_kf16);
    cudaGetSymbolAddress((void**)&p_vf16,  g_vf16);

    cudaFuncSetAttribute(gemm_qkv_gate, cudaFuncAttributeMaxDynamicSharedMemorySize,
                         GEMM_SMEM_BYTES);
    cudaFuncSetAttribute(gemm_proj, cudaFuncAttributeMaxDynamicSharedMemorySize,
                         GEMM_SMEM_BYTES);
    cudaFuncSetAttribute(attn_kernel, cudaFuncAttributeMaxDynamicSharedMemorySize,
                         ATTN_SMEM_BYTES);

    // 0. fused: weight transposes + LayerNorm (one launch)
    lt_kernel<<<NTRB + BL, 256>>>(W_qkv, W_gate, W_proj, p_wtq, p_wtg, p_wtp,
                                  x, ln_g, ln_b, p_an, p_x16);

    // 1. fused QKV + gate GEMM (q,v finished in epilogue; k -> fp16 kraw16)
    gemm_qkv_gate<<<dim3(N3D / 128 + D2 / 128, BL / 128), 256, GEMM_SMEM_BYTES>>>(
        p_an, p_wtq, b_qkv, p_qf16, p_vf16, p_kraw16,
        p_x16, p_wtg, b_gate, gate);

    // 2. per-chunk: gate+elu+1 on k, K^T V via MMA, kf16 out
    chunk_kv_kernel<<<dim3(NC, BH), 256>>>(p_kraw16, gate, p_vf16, p_kf16, p_kv, p_ksum);

    // 3. per-chunk attention via MMA (chunk-prefix fused in)
    attn_kernel<<<dim3(NC, BH), 256, ATTN_SMEM_BYTES>>>(
        p_qf16, p_kf16, p_vf16, p_kv, p_ksum, p_at16);

    // 4. out = attn @ W_proj + b_proj
    gemm_proj<<<dim3(D2 / 128, BL / 128), 256, GEMM_SMEM_BYTES>>>(
        p_at16, p_wtp, b_proj, out);
}